// round 12
// baseline (speedup 1.0000x reference)
#include <cuda_runtime.h>
#include <cuda_bf16.h>
#include <mma.h>
#include <stdint.h>
#include <math.h>

using namespace nvcuda;

#define BB 32
#define TT 1024
#define JJ 256
#define DD 512

// ------------------- device scratch (no runtime alloc) ----------------------
__device__ float g_S[(size_t)BB * TT * JJ];
__device__ __nv_bfloat16 g_Ahi[(size_t)BB * TT * DD];  // split(ctx*w3)
__device__ __nv_bfloat16 g_Alo[(size_t)BB * TT * DD];
__device__ __nv_bfloat16 g_Bhi[(size_t)BB * JJ * DD];  // split(q) [b,j,d]
__device__ __nv_bfloat16 g_Blo[(size_t)BB * JJ * DD];
__device__ float g_a[BB * TT], g_c[BB * JJ];
__device__ float g_rm[BB * TT];
__device__ float g_h[BB * DD];
__device__ float g_pm[BB * 16 * JJ], g_ps[BB * 16 * JJ];

// ------------------------------ helpers -------------------------------------
__device__ __forceinline__ uint32_t smem_u32(const void* p) {
    uint32_t a;
    asm("{ .reg .u64 t; cvta.to.shared.u64 t, %1; cvt.u32.u64 %0, t; }"
        : "=r"(a) : "l"(p));
    return a;
}
__device__ __forceinline__ void cpa16(uint32_t d, const void* s) {
    asm volatile("cp.async.cg.shared.global [%0], [%1], 16;" :: "r"(d), "l"(s));
}
__device__ __forceinline__ void cpa_commit() {
    asm volatile("cp.async.commit_group;" ::: "memory");
}
template <int N>
__device__ __forceinline__ void cpa_wait() {
    asm volatile("cp.async.wait_group %0;" :: "n"(N) : "memory");
}

// Fast exp on the FMA pipe (no MUFU). Valid for x <= ~0 (softmax args);
// clamps at -100 so the exponent bit-trick stays in normal range.
// exp(x) = 2^(x*log2e); n = rint(y); 2^f via degree-5 minimax on [-0.5, 0.5].
__device__ __forceinline__ float fexp(float x) {
    float y = fmaxf(x * 1.4426950408889634f, -100.f);
    float n = rintf(y);
    float f = y - n;
    float p = 1.33335581464e-3f;
    p = fmaf(p, f, 9.61812910763e-3f);
    p = fmaf(p, f, 5.55041086648e-2f);
    p = fmaf(p, f, 2.40226506959e-1f);
    p = fmaf(p, f, 6.93147180560e-1f);
    p = fmaf(p, f, 1.0f);
    return __int_as_float(__float_as_int(p) + (((int)n) << 23));
}

__device__ __forceinline__ void split4(float x0, float x1, float x2, float x3,
                                       uint2& hi, uint2& lo) {
    __nv_bfloat16 h0 = __float2bfloat16(x0), h1 = __float2bfloat16(x1);
    __nv_bfloat16 h2 = __float2bfloat16(x2), h3 = __float2bfloat16(x3);
    __nv_bfloat16 l0 = __float2bfloat16(x0 - __bfloat162float(h0));
    __nv_bfloat16 l1 = __float2bfloat16(x1 - __bfloat162float(h1));
    __nv_bfloat16 l2 = __float2bfloat16(x2 - __bfloat162float(h2));
    __nv_bfloat16 l3 = __float2bfloat16(x3 - __bfloat162float(h3));
    hi.x = ((uint32_t)__bfloat16_as_ushort(h1) << 16) | __bfloat16_as_ushort(h0);
    hi.y = ((uint32_t)__bfloat16_as_ushort(h3) << 16) | __bfloat16_as_ushort(h2);
    lo.x = ((uint32_t)__bfloat16_as_ushort(l1) << 16) | __bfloat16_as_ushort(l0);
    lo.y = ((uint32_t)__bfloat16_as_ushort(l3) << 16) | __bfloat16_as_ushort(l2);
}

// ------------------------- layout constants ---------------------------------
#define LDSA 40        // 32 k + 8 pad (80B rows)
#define MATA 5120      // 64*40*2 (A matrix: 64 rows, both gemms)
#define MATB1 20480
#define STG1 51200     // 2*5120 + 2*20480
#define G1_AS (2 * STG1)
#define G1_CS (G1_AS + 256)
#define SMB1 (G1_CS + 1024)
#define LDSB2 264
#define MATB2 16896
#define STG2 44032     // 2*5120 + 2*16896
#define G2_CM (2 * STG2)
#define G2_CI (G2_CM + 1024)
#define G2_HS (G2_CI + 1024)
#define SMB2 (G2_HS + 1024)

typedef wmma::fragment<wmma::accumulator, 16, 16, 16, float> AccFrag;
typedef wmma::fragment<wmma::matrix_a, 16, 16, 16, __nv_bfloat16, wmma::row_major> AFrag;
typedef wmma::fragment<wmma::matrix_b, 16, 16, 16, __nv_bfloat16, wmma::col_major> BFragC;
typedef wmma::fragment<wmma::matrix_b, 16, 16, 16, __nv_bfloat16, wmma::row_major> BFragR;

// one K=32 chunk, gemm1 flavor (B col-major [n][k]); warp tile 32x64, warps 2x4
__device__ __forceinline__ void chunk_g1(const char* smc, int bo, int wm, int wn,
                                         AccFrag acc[2][4]) {
    const __nv_bfloat16* Ah = (const __nv_bfloat16*)(smc + bo);
    const __nv_bfloat16* Al = (const __nv_bfloat16*)(smc + bo + MATA);
    const __nv_bfloat16* Bh = (const __nv_bfloat16*)(smc + bo + 2 * MATA);
    const __nv_bfloat16* Bl = (const __nv_bfloat16*)(smc + bo + 2 * MATA + MATB1);
#pragma unroll
    for (int k0 = 0; k0 < 32; k0 += 16) {
        AFrag ah[2], al[2];
#pragma unroll
        for (int i = 0; i < 2; i++) {
            wmma::load_matrix_sync(ah[i], Ah + (wm * 32 + i * 16) * LDSA + k0, LDSA);
            wmma::load_matrix_sync(al[i], Al + (wm * 32 + i * 16) * LDSA + k0, LDSA);
        }
#pragma unroll
        for (int jh = 0; jh < 2; jh++) {
            BFragC bh[2], bl[2];
#pragma unroll
            for (int j = 0; j < 2; j++)
                wmma::load_matrix_sync(bh[j], Bh + (wn * 64 + jh * 32 + j * 16) * LDSA + k0, LDSA);
#pragma unroll
            for (int i = 0; i < 2; i++)
#pragma unroll
                for (int j = 0; j < 2; j++)
                    wmma::mma_sync(acc[i][jh * 2 + j], ah[i], bh[j], acc[i][jh * 2 + j]);
#pragma unroll
            for (int j = 0; j < 2; j++)
                wmma::load_matrix_sync(bl[j], Bl + (wn * 64 + jh * 32 + j * 16) * LDSA + k0, LDSA);
#pragma unroll
            for (int i = 0; i < 2; i++)
#pragma unroll
                for (int j = 0; j < 2; j++)
                    wmma::mma_sync(acc[i][jh * 2 + j], ah[i], bl[j], acc[i][jh * 2 + j]);
#pragma unroll
            for (int i = 0; i < 2; i++)
#pragma unroll
                for (int j = 0; j < 2; j++)
                    wmma::mma_sync(acc[i][jh * 2 + j], al[i], bh[j], acc[i][jh * 2 + j]);
        }
    }
}

// one K=32 chunk, gemm2 flavor (B row-major [k][n]); warp tile 32x64, warps 2x4
__device__ __forceinline__ void chunk_g2(const char* smc, int bo, int wm, int wn,
                                         AccFrag acc[2][4]) {
    const __nv_bfloat16* Ah = (const __nv_bfloat16*)(smc + bo);
    const __nv_bfloat16* Al = (const __nv_bfloat16*)(smc + bo + MATA);
    const __nv_bfloat16* Bh = (const __nv_bfloat16*)(smc + bo + 2 * MATA);
    const __nv_bfloat16* Bl = (const __nv_bfloat16*)(smc + bo + 2 * MATA + MATB2);
#pragma unroll
    for (int k0 = 0; k0 < 32; k0 += 16) {
        AFrag ah[2], al[2];
#pragma unroll
        for (int i = 0; i < 2; i++) {
            wmma::load_matrix_sync(ah[i], Ah + (wm * 32 + i * 16) * LDSA + k0, LDSA);
            wmma::load_matrix_sync(al[i], Al + (wm * 32 + i * 16) * LDSA + k0, LDSA);
        }
#pragma unroll
        for (int jh = 0; jh < 2; jh++) {
            BFragR bh[2], bl[2];
#pragma unroll
            for (int j = 0; j < 2; j++)
                wmma::load_matrix_sync(bh[j], Bh + k0 * LDSB2 + wn * 64 + jh * 32 + j * 16, LDSB2);
#pragma unroll
            for (int i = 0; i < 2; i++)
#pragma unroll
                for (int j = 0; j < 2; j++)
                    wmma::mma_sync(acc[i][jh * 2 + j], ah[i], bh[j], acc[i][jh * 2 + j]);
#pragma unroll
            for (int j = 0; j < 2; j++)
                wmma::load_matrix_sync(bl[j], Bl + k0 * LDSB2 + wn * 64 + jh * 32 + j * 16, LDSB2);
#pragma unroll
            for (int i = 0; i < 2; i++)
#pragma unroll
                for (int j = 0; j < 2; j++)
                    wmma::mma_sync(acc[i][jh * 2 + j], ah[i], bl[j], acc[i][jh * 2 + j]);
#pragma unroll
            for (int i = 0; i < 2; i++)
#pragma unroll
                for (int j = 0; j < 2; j++)
                    wmma::mma_sync(acc[i][jh * 2 + j], al[i], bh[j], acc[i][jh * 2 + j]);
        }
    }
}

// ---------------------------------------------------------------------------
// K1: split(ctx*w3)->Ahi/Alo + a=ctx.w1 ; split(q)->Bhi/Blo + c=q.w2
// ---------------------------------------------------------------------------
__global__ void convert_kernel(const float* __restrict__ ctx,
                               const float* __restrict__ qry,
                               const float* __restrict__ w) {
    int gw = (blockIdx.x * blockDim.x + threadIdx.x) >> 5;
    int lane = threadIdx.x & 31;
    if (gw < BB * TT) {
        const float* row = ctx + (size_t)gw * DD;
        float acc = 0.f;
#pragma unroll
        for (int i = 0; i < 4; i++) {
            int col = i * 128 + lane * 4;
            float4 x = *(const float4*)(row + col);
            float4 w1v = *(const float4*)(w + col);
            acc += x.x * w1v.x + x.y * w1v.y + x.z * w1v.z + x.w * w1v.w;
            float4 w3v = *(const float4*)(w + 2 * DD + col);
            uint2 hi, lo;
            split4(x.x * w3v.x, x.y * w3v.y, x.z * w3v.z, x.w * w3v.w, hi, lo);
            size_t o = (size_t)gw * DD + col;
            *(uint2*)((char*)g_Ahi + o * 2) = hi;
            *(uint2*)((char*)g_Alo + o * 2) = lo;
        }
#pragma unroll
        for (int o = 16; o; o >>= 1) acc += __shfl_xor_sync(~0u, acc, o);
        if (lane == 0) g_a[gw] = acc;
    } else {
        int r = gw - BB * TT;
        if (r >= BB * JJ) return;
        const float* row = qry + (size_t)r * DD;
        float acc = 0.f;
#pragma unroll
        for (int i = 0; i < 4; i++) {
            int col = i * 128 + lane * 4;
            float4 x = *(const float4*)(row + col);
            float4 w2v = *(const float4*)(w + DD + col);
            acc += x.x * w2v.x + x.y * w2v.y + x.z * w2v.z + x.w * w2v.w;
            uint2 hi, lo;
            split4(x.x, x.y, x.z, x.w, hi, lo);
            size_t o = (size_t)r * DD + col;
            *(uint2*)((char*)g_Bhi + o * 2) = hi;
            *(uint2*)((char*)g_Blo + o * 2) = lo;
        }
#pragma unroll
        for (int o = 16; o; o >>= 1) acc += __shfl_xor_sync(~0u, acc, o);
        if (lane == 0) g_c[r] = acc;
    }
}

// ---------------------------------------------------------------------------
// K2: GEMM1 (WMMA, 256 thr, 2 CTA/SM): S[b, m0:+64, 0:256] (full J per CTA)
//     fused rowmax + fused column softmax partials (16 per b)
// ---------------------------------------------------------------------------
__global__ __launch_bounds__(256, 2) void gemm1_wmma() {
    extern __shared__ __align__(16) char smc[];
    int tid = threadIdx.x;
    int wid = tid >> 5, wm = wid >> 2, wn = wid & 3;
    int lane = tid & 31;
    int b = blockIdx.y, mt = blockIdx.x, m0 = mt * 64;

    float* a_s = (float*)(smc + G1_AS);
    float* c_s = (float*)(smc + G1_CS);
    if (tid < 64) a_s[tid] = g_a[b * TT + m0 + tid];
    c_s[tid] = g_c[b * JJ + tid];

    const __nv_bfloat16* Ah = g_Ahi + (size_t)(b * TT + m0) * DD;
    const __nv_bfloat16* Al = g_Alo + (size_t)(b * TT + m0) * DD;
    const __nv_bfloat16* Bh = g_Bhi + (size_t)b * JJ * DD;
    const __nv_bfloat16* Bl = g_Blo + (size_t)b * JJ * DD;
    uint32_t sm0 = smem_u32(smc);

    AccFrag acc[2][4];
#pragma unroll
    for (int i = 0; i < 2; i++)
#pragma unroll
        for (int j = 0; j < 4; j++) wmma::fill_fragment(acc[i][j], 0.f);

    auto load_stage = [&](int stg, int kc) {
#pragma unroll 1
        for (int i = tid; i < 512; i += 256) {
            int which = i >> 8, idx = i & 255;
            int row = idx >> 2, seg = idx & 3;
            const __nv_bfloat16* src = (which ? Al : Ah) + (size_t)row * DD + kc + seg * 8;
            cpa16(sm0 + stg + which * MATA + row * 80 + seg * 16, src);
        }
#pragma unroll 1
        for (int i = tid; i < 2048; i += 256) {
            int which = i >> 10, idx = i & 1023;
            int row = idx >> 2, seg = idx & 3;
            const __nv_bfloat16* src = (which ? Bl : Bh) + (size_t)row * DD + kc + seg * 8;
            cpa16(sm0 + stg + 2 * MATA + which * MATB1 + row * 80 + seg * 16, src);
        }
        cpa_commit();
    };

    load_stage(0, 0);
    for (int c = 0; c < 16; c++) {
        int cb = (c & 1) * STG1;
        if (c + 1 < 16) {
            load_stage(((c + 1) & 1) * STG1, (c + 1) * 32);
            cpa_wait<1>();
        } else {
            cpa_wait<0>();
        }
        __syncthreads();
        chunk_g1(smc, cb, wm, wn, acc);
        __syncthreads();
    }

    // epilogue: stage 64x256 to smem (ld 260), bias, coalesced write + rowmax
    float* Su = (float*)smc;
#pragma unroll
    for (int i = 0; i < 2; i++)
#pragma unroll
        for (int j = 0; j < 4; j++)
            wmma::store_matrix_sync(Su + (wm * 32 + i * 16) * 260 + wn * 64 + j * 16,
                                    acc[i][j], 260, wmma::mem_row_major);
    __syncthreads();
    float* Sg = g_S + (size_t)(b * TT + m0) * JJ;
    int c4a = lane * 4, c4b = 128 + lane * 4;
#pragma unroll 1
    for (int r0 = 0; r0 < 64; r0 += 8) {
        int row = r0 + wid;
        float av = a_s[row];
        float4 v1 = *(float4*)&Su[row * 260 + c4a];
        float4 cv1 = *(float4*)&c_s[c4a];
        v1.x += av + cv1.x; v1.y += av + cv1.y; v1.z += av + cv1.z; v1.w += av + cv1.w;
        float4 v2 = *(float4*)&Su[row * 260 + c4b];
        float4 cv2 = *(float4*)&c_s[c4b];
        v2.x += av + cv2.x; v2.y += av + cv2.y; v2.z += av + cv2.z; v2.w += av + cv2.w;
        *(float4*)(Sg + (size_t)row * JJ + c4a) = v1;
        *(float4*)(Sg + (size_t)row * JJ + c4b) = v2;
        float rm = fmaxf(fmaxf(fmaxf(v1.x, v1.y), fmaxf(v1.z, v1.w)),
                         fmaxf(fmaxf(v2.x, v2.y), fmaxf(v2.z, v2.w)));
#pragma unroll
        for (int o = 16; o; o >>= 1) rm = fmaxf(rm, __shfl_xor_sync(~0u, rm, o));
        if (lane == 0) g_rm[b * TT + m0 + row] = rm;
    }

    // fused column softmax partials: per-column two-pass (max, then sum-exp)
    int col = tid;
    float cval = c_s[col];
    float m = -3.0e38f;
#pragma unroll 1
    for (int r = 0; r < 64; r++)
        m = fmaxf(m, Su[r * 260 + col] + a_s[r] + cval);
    float s = 0.f;
#pragma unroll 1
    for (int r = 0; r < 64; r++)
        s += fexp(Su[r * 260 + col] + a_s[r] + cval - m);
    g_pm[(b * 16 + mt) * JJ + col] = m;
    g_ps[(b * 16 + mt) * JJ + col] = s;
}

// ---------------------------------------------------------------------------
// K3: b_t = softmax_t(rowmax); h[b,d] = sum_t b_t * ctx
// ---------------------------------------------------------------------------
__global__ __launch_bounds__(128) void bth_kernel(const float* __restrict__ ctx) {
    int b = blockIdx.y, q = blockIdx.x, tid = threadIdx.x;
    int wid = tid >> 5, lane = tid & 31;
    __shared__ float e_s[TT];
    __shared__ float red_m[4], red_s[4];
    float v[8];
    float m = -3.0e38f;
#pragma unroll
    for (int i = 0; i < 8; i++) {
        v[i] = g_rm[b * TT + tid + i * 128];
        m = fmaxf(m, v[i]);
    }
#pragma unroll
    for (int o = 16; o; o >>= 1) m = fmaxf(m, __shfl_xor_sync(~0u, m, o));
    if (lane == 0) red_m[wid] = m;
    __syncthreads();
    m = fmaxf(fmaxf(red_m[0], red_m[1]), fmaxf(red_m[2], red_m[3]));
    float s = 0.f;
#pragma unroll
    for (int i = 0; i < 8; i++) {
        float e = fexp(v[i] - m);
        e_s[tid + i * 128] = e;
        s += e;
    }
#pragma unroll
    for (int o = 16; o; o >>= 1) s += __shfl_xor_sync(~0u, s, o);
    if (lane == 0) red_s[wid] = s;
    __syncthreads();
    float inv = 1.f / (red_s[0] + red_s[1] + red_s[2] + red_s[3]);
    int d = q * 128 + tid;
    const float* cb = ctx + (size_t)b * TT * DD + d;
    float a0 = 0.f, a1 = 0.f, a2 = 0.f, a3 = 0.f;
    for (int t = 0; t < TT; t += 4) {
        a0 += e_s[t + 0] * cb[(size_t)(t + 0) * DD];
        a1 += e_s[t + 1] * cb[(size_t)(t + 1) * DD];
        a2 += e_s[t + 2] * cb[(size_t)(t + 2) * DD];
        a3 += e_s[t + 3] * cb[(size_t)(t + 3) * DD];
    }
    g_h[b * DD + d] = (a0 + a1 + a2 + a3) * inv;
}

// ---------------------------------------------------------------------------
// K4: GEMM2 (WMMA, 256 thr, 2 CTA/SM): U tile 64x256 = softmax_col(S) @ q
//     colstats combine in prologue; fused G epilogue
// ---------------------------------------------------------------------------
__global__ __launch_bounds__(256, 2) void gemm2_wmma(const float* __restrict__ ctx,
                                                     float* __restrict__ out) {
    extern __shared__ __align__(16) char smc[];
    int tid = threadIdx.x;
    int wid = tid >> 5, wm = wid >> 2, wn = wid & 3;
    int lane = tid & 31;
    int b = blockIdx.z, m0 = blockIdx.y * 64, n0 = blockIdx.x * 256;

    float* cm_s = (float*)(smc + G2_CM);
    float* ci_s = (float*)(smc + G2_CI);
    float* h_s = (float*)(smc + G2_HS);
    {
        float M = -3.0e38f;
#pragma unroll
        for (int p = 0; p < 16; p++) M = fmaxf(M, g_pm[(b * 16 + p) * JJ + tid]);
        float S = 0.f;
#pragma unroll
        for (int p = 0; p < 16; p++)
            S += g_ps[(b * 16 + p) * JJ + tid] * fexp(g_pm[(b * 16 + p) * JJ + tid] - M);
        cm_s[tid] = M;
        ci_s[tid] = 1.f / S;
        h_s[tid] = g_h[b * DD + n0 + tid];
    }
    __syncthreads();

    const float* Sg = g_S + (size_t)(b * TT + m0) * JJ;
    const __nv_bfloat16* Bh = g_Bhi + (size_t)b * JJ * DD + n0;
    const __nv_bfloat16* Bl = g_Blo + (size_t)b * JJ * DD + n0;
    uint32_t sm0 = smem_u32(smc);

    AccFrag acc[2][4];
#pragma unroll
    for (int i = 0; i < 2; i++)
#pragma unroll
        for (int j = 0; j < 4; j++) wmma::fill_fragment(acc[i][j], 0.f);

    auto load_stage = [&](int stg, int kc) {
#pragma unroll 1
        for (int i = tid; i < 2048; i += 256) {
            int which = i >> 10, idx = i & 1023;
            int row = idx >> 5, seg = idx & 31;
            const __nv_bfloat16* src =
                (which ? Bl : Bh) + (size_t)(kc + row) * DD + seg * 8;
            cpa16(sm0 + stg + 2 * MATA + which * MATB2 + row * 528 + seg * 16, src);
        }
        cpa_commit();
#pragma unroll 1
        for (int i = tid; i < 512; i += 256) {
            int row = i >> 3, c4 = (i & 7) * 4;
            int jb = kc + c4;
            float4 v = *(const float4*)(Sg + (size_t)row * JJ + jb);
            float p0 = fexp(v.x - cm_s[jb + 0]) * ci_s[jb + 0];
            float p1 = fexp(v.y - cm_s[jb + 1]) * ci_s[jb + 1];
            float p2 = fexp(v.z - cm_s[jb + 2]) * ci_s[jb + 2];
            float p3 = fexp(v.w - cm_s[jb + 3]) * ci_s[jb + 3];
            uint2 hi, lo;
            split4(p0, p1, p2, p3, hi, lo);
            *(uint2*)(smc + stg + row * 80 + c4 * 2) = hi;
            *(uint2*)(smc + stg + MATA + row * 80 + c4 * 2) = lo;
        }
    };

    load_stage(0, 0);
    for (int c = 0; c < 8; c++) {
        int cb = (c & 1) * STG2;
        if (c + 1 < 8) {
            load_stage(((c + 1) & 1) * STG2, (c + 1) * 32);
            cpa_wait<1>();
        } else {
            cpa_wait<0>();
        }
        __syncthreads();
        chunk_g2(smc, cb, wm, wn, acc);
        __syncthreads();
    }

    // epilogue: stage U (64x256, ld 260), fused G = [ctx, U, ctx*U, ctx*h]
    float* Su = (float*)smc;
#pragma unroll
    for (int i = 0; i < 2; i++)
#pragma unroll
        for (int j = 0; j < 4; j++)
            wmma::store_matrix_sync(Su + (wm * 32 + i * 16) * 260 + wn * 64 + j * 16,
                                    acc[i][j], 260, wmma::mem_row_major);
    __syncthreads();
    int c4a = lane * 4, c4b = 128 + lane * 4;
#pragma unroll 1
    for (int r0 = 0; r0 < 64; r0 += 8) {
        int row = r0 + wid;
        const float* crow = ctx + (size_t)(b * TT + m0 + row) * DD + n0;
        float* og = out + (size_t)(b * TT + m0 + row) * 2048 + n0;
#pragma unroll
        for (int half = 0; half < 2; half++) {
            int c4 = half ? c4b : c4a;
            float4 u = *(float4*)&Su[row * 260 + c4];
            float4 cx = *(const float4*)(crow + c4);
            float4 h4 = *(float4*)&h_s[c4];
            float4 cu, ch;
            cu.x = cx.x * u.x; cu.y = cx.y * u.y; cu.z = cx.z * u.z; cu.w = cx.w * u.w;
            ch.x = cx.x * h4.x; ch.y = cx.y * h4.y; ch.z = cx.z * h4.z; ch.w = cx.w * h4.w;
            *(float4*)(og + c4) = cx;
            *(float4*)(og + 512 + c4) = u;
            *(float4*)(og + 1024 + c4) = cu;
            *(float4*)(og + 1536 + c4) = ch;
        }
    }
}

// ---------------------------------------------------------------------------
extern "C" void kernel_launch(void* const* d_in, const int* in_sizes, int n_in,
                              void* d_out, int out_size) {
    const float* ctx = (const float*)d_in[0];
    const float* qry = (const float*)d_in[1];
    const float* w = (const float*)d_in[2];
    float* out = (float*)d_out;

    cudaFuncSetAttribute(gemm1_wmma, cudaFuncAttributeMaxDynamicSharedMemorySize, SMB1);
    cudaFuncSetAttribute(gemm2_wmma, cudaFuncAttributeMaxDynamicSharedMemorySize, SMB2);

    convert_kernel<<<(BB * TT + BB * JJ) / 8, 256>>>(ctx, qry, w);
    gemm1_wmma<<<dim3(TT / 64, BB), 256, SMB1>>>();
    bth_kernel<<<dim3(4, BB), 128>>>(ctx);
    gemm2_wmma<<<dim3(DD / 256, TT / 64, BB), 256, SMB2>>>(ctx, out);
}

// round 14
// speedup vs baseline: 1.3983x; 1.3983x over previous
#include <cuda_runtime.h>
#include <cuda_fp16.h>
#include <mma.h>
#include <stdint.h>
#include <math.h>

using namespace nvcuda;

#define BB 32
#define TT 1024
#define JJ 256
#define DD 512

// ------------------- device scratch (no runtime alloc) ----------------------
__device__ float g_S[(size_t)BB * TT * JJ];
__device__ __half g_Af16[(size_t)BB * TT * DD];  // fp16(ctx*w3)
__device__ __half g_Bf16[(size_t)BB * JJ * DD];  // fp16(q) [b,j,d]
__device__ float g_a[BB * TT], g_c[BB * JJ];
__device__ float g_rm[BB * TT];
__device__ float g_h[BB * DD];
__device__ float g_pm[BB * 16 * JJ], g_ps[BB * 16 * JJ];

// ------------------------------ helpers -------------------------------------
__device__ __forceinline__ uint32_t smem_u32(const void* p) {
    uint32_t a;
    asm("{ .reg .u64 t; cvta.to.shared.u64 t, %1; cvt.u32.u64 %0, t; }"
        : "=r"(a) : "l"(p));
    return a;
}
__device__ __forceinline__ void cpa16(uint32_t d, const void* s) {
    asm volatile("cp.async.cg.shared.global [%0], [%1], 16;" :: "r"(d), "l"(s));
}
__device__ __forceinline__ void cpa_commit() {
    asm volatile("cp.async.commit_group;" ::: "memory");
}
template <int N>
__device__ __forceinline__ void cpa_wait() {
    asm volatile("cp.async.wait_group %0;" :: "n"(N) : "memory");
}

__device__ __forceinline__ uint2 pack4h(float x0, float x1, float x2, float x3) {
    __half2 u = __floats2half2_rn(x0, x1);
    __half2 v = __floats2half2_rn(x2, x3);
    uint2 r;
    r.x = *(uint32_t*)&u;
    r.y = *(uint32_t*)&v;
    return r;
}

// ------------------------- layout constants ---------------------------------
#define LDSA 40        // 32 k + 8 pad (80B rows, half)
#define MATA 5120      // 64*40*2
// gemm1: B = 256 rows x 40 halves (k-major)
#define MATB1 20480
#define STG1 25600     // MATA + MATB1
#define G1_AS 66560    // after Su (64*260*4)
#define G1_CS (G1_AS + 256)
#define SMB1 (G1_CS + 1024)
// gemm2: B = 32 rows x 264 halves (n-major, 528B rows)
#define LDSB2 264
#define MATB2 16896
#define STG2 22016     // MATA + MATB2
#define G2_CM 66560
#define G2_CI (G2_CM + 1024)
#define G2_HS (G2_CI + 1024)
#define SMB2 (G2_HS + 1024)

typedef wmma::fragment<wmma::accumulator, 16, 16, 16, float> AccFrag;
typedef wmma::fragment<wmma::matrix_a, 16, 16, 16, __half, wmma::row_major> AFrag;
typedef wmma::fragment<wmma::matrix_b, 16, 16, 16, __half, wmma::col_major> BFragC;
typedef wmma::fragment<wmma::matrix_b, 16, 16, 16, __half, wmma::row_major> BFragR;

// one K=32 chunk, gemm1 flavor (B col-major [n][k]); warp tile 32x64
__device__ __forceinline__ void chunk_g1(const char* smc, int bo, int wm, int wn,
                                         AccFrag acc[2][4]) {
    const __half* A = (const __half*)(smc + bo);
    const __half* B = (const __half*)(smc + bo + MATA);
#pragma unroll
    for (int k0 = 0; k0 < 32; k0 += 16) {
        AFrag a[2];
#pragma unroll
        for (int i = 0; i < 2; i++)
            wmma::load_matrix_sync(a[i], A + (wm * 32 + i * 16) * LDSA + k0, LDSA);
#pragma unroll
        for (int jh = 0; jh < 2; jh++) {
            BFragC b[2];
#pragma unroll
            for (int j = 0; j < 2; j++)
                wmma::load_matrix_sync(b[j], B + (wn * 64 + jh * 32 + j * 16) * LDSA + k0, LDSA);
#pragma unroll
            for (int i = 0; i < 2; i++)
#pragma unroll
                for (int j = 0; j < 2; j++)
                    wmma::mma_sync(acc[i][jh * 2 + j], a[i], b[j], acc[i][jh * 2 + j]);
        }
    }
}

// one K=32 chunk, gemm2 flavor (B row-major [k][n]); warp tile 32x64
__device__ __forceinline__ void chunk_g2(const char* smc, int bo, int wm, int wn,
                                         AccFrag acc[2][4]) {
    const __half* A = (const __half*)(smc + bo);
    const __half* B = (const __half*)(smc + bo + MATA);
#pragma unroll
    for (int k0 = 0; k0 < 32; k0 += 16) {
        AFrag a[2];
#pragma unroll
        for (int i = 0; i < 2; i++)
            wmma::load_matrix_sync(a[i], A + (wm * 32 + i * 16) * LDSA + k0, LDSA);
#pragma unroll
        for (int jh = 0; jh < 2; jh++) {
            BFragR b[2];
#pragma unroll
            for (int j = 0; j < 2; j++)
                wmma::load_matrix_sync(b[j], B + k0 * LDSB2 + wn * 64 + jh * 32 + j * 16, LDSB2);
#pragma unroll
            for (int i = 0; i < 2; i++)
#pragma unroll
                for (int j = 0; j < 2; j++)
                    wmma::mma_sync(acc[i][jh * 2 + j], a[i], b[j], acc[i][jh * 2 + j]);
        }
    }
}

// ---------------------------------------------------------------------------
// K1: Af16 = fp16(ctx*w3), a = ctx.w1 ; Bf16 = fp16(q), c = q.w2
// ---------------------------------------------------------------------------
__global__ void convert_kernel(const float* __restrict__ ctx,
                               const float* __restrict__ qry,
                               const float* __restrict__ w) {
    int gw = (blockIdx.x * blockDim.x + threadIdx.x) >> 5;
    int lane = threadIdx.x & 31;
    if (gw < BB * TT) {
        const float* row = ctx + (size_t)gw * DD;
        float acc = 0.f;
#pragma unroll
        for (int i = 0; i < 4; i++) {
            int col = i * 128 + lane * 4;
            float4 x = *(const float4*)(row + col);
            float4 w1v = *(const float4*)(w + col);
            acc += x.x * w1v.x + x.y * w1v.y + x.z * w1v.z + x.w * w1v.w;
            float4 w3v = *(const float4*)(w + 2 * DD + col);
            uint2 hv = pack4h(x.x * w3v.x, x.y * w3v.y, x.z * w3v.z, x.w * w3v.w);
            *(uint2*)((char*)g_Af16 + ((size_t)gw * DD + col) * 2) = hv;
        }
#pragma unroll
        for (int o = 16; o; o >>= 1) acc += __shfl_xor_sync(~0u, acc, o);
        if (lane == 0) g_a[gw] = acc;
    } else {
        int r = gw - BB * TT;
        if (r >= BB * JJ) return;
        const float* row = qry + (size_t)r * DD;
        float acc = 0.f;
#pragma unroll
        for (int i = 0; i < 4; i++) {
            int col = i * 128 + lane * 4;
            float4 x = *(const float4*)(row + col);
            float4 w2v = *(const float4*)(w + DD + col);
            acc += x.x * w2v.x + x.y * w2v.y + x.z * w2v.z + x.w * w2v.w;
            uint2 hv = pack4h(x.x, x.y, x.z, x.w);
            *(uint2*)((char*)g_Bf16 + ((size_t)r * DD + col) * 2) = hv;
        }
#pragma unroll
        for (int o = 16; o; o >>= 1) acc += __shfl_xor_sync(~0u, acc, o);
        if (lane == 0) g_c[r] = acc;
    }
}

// ---------------------------------------------------------------------------
// K2: GEMM1 (fp16 WMMA, 256 thr, 2 CTA/SM): S[b, m0:+64, 0:256]
//     fused rowmax + fused column softmax partials (16 per b)
// ---------------------------------------------------------------------------
__global__ __launch_bounds__(256, 2) void gemm1_wmma() {
    extern __shared__ __align__(16) char smc[];
    int tid = threadIdx.x;
    int wid = tid >> 5, wm = wid >> 2, wn = wid & 3;
    int lane = tid & 31;
    int b = blockIdx.y, mt = blockIdx.x, m0 = mt * 64;

    float* a_s = (float*)(smc + G1_AS);
    float* c_s = (float*)(smc + G1_CS);
    if (tid < 64) a_s[tid] = g_a[b * TT + m0 + tid];
    c_s[tid] = g_c[b * JJ + tid];

    const __half* Ag = g_Af16 + (size_t)(b * TT + m0) * DD;
    const __half* Bg = g_Bf16 + (size_t)b * JJ * DD;
    uint32_t sm0 = smem_u32(smc);

    AccFrag acc[2][4];
#pragma unroll
    for (int i = 0; i < 2; i++)
#pragma unroll
        for (int j = 0; j < 4; j++) wmma::fill_fragment(acc[i][j], 0.f);

    auto load_stage = [&](int stg, int kc) {
#pragma unroll 1
        for (int i = tid; i < 256; i += 256) {
            int row = i >> 2, seg = i & 3;
            cpa16(sm0 + stg + row * 80 + seg * 16, Ag + (size_t)row * DD + kc + seg * 8);
        }
#pragma unroll 1
        for (int i = tid; i < 1024; i += 256) {
            int row = i >> 2, seg = i & 3;
            cpa16(sm0 + stg + MATA + row * 80 + seg * 16, Bg + (size_t)row * DD + kc + seg * 8);
        }
        cpa_commit();
    };

    load_stage(0, 0);
    for (int c = 0; c < 16; c++) {
        int cb = (c & 1) * STG1;
        if (c + 1 < 16) {
            load_stage(((c + 1) & 1) * STG1, (c + 1) * 32);
            cpa_wait<1>();
        } else {
            cpa_wait<0>();
        }
        __syncthreads();
        chunk_g1(smc, cb, wm, wn, acc);
        __syncthreads();
    }

    // epilogue: stage 64x256 to smem (ld 260), bias, coalesced write + rowmax
    float* Su = (float*)smc;
#pragma unroll
    for (int i = 0; i < 2; i++)
#pragma unroll
        for (int j = 0; j < 4; j++)
            wmma::store_matrix_sync(Su + (wm * 32 + i * 16) * 260 + wn * 64 + j * 16,
                                    acc[i][j], 260, wmma::mem_row_major);
    __syncthreads();
    float* Sg = g_S + (size_t)(b * TT + m0) * JJ;
    int c4a = lane * 4, c4b = 128 + lane * 4;
#pragma unroll 1
    for (int r0 = 0; r0 < 64; r0 += 8) {
        int row = r0 + wid;
        float av = a_s[row];
        float4 v1 = *(float4*)&Su[row * 260 + c4a];
        float4 cv1 = *(float4*)&c_s[c4a];
        v1.x += av + cv1.x; v1.y += av + cv1.y; v1.z += av + cv1.z; v1.w += av + cv1.w;
        float4 v2 = *(float4*)&Su[row * 260 + c4b];
        float4 cv2 = *(float4*)&c_s[c4b];
        v2.x += av + cv2.x; v2.y += av + cv2.y; v2.z += av + cv2.z; v2.w += av + cv2.w;
        *(float4*)(Sg + (size_t)row * JJ + c4a) = v1;
        *(float4*)(Sg + (size_t)row * JJ + c4b) = v2;
        float rm = fmaxf(fmaxf(fmaxf(v1.x, v1.y), fmaxf(v1.z, v1.w)),
                         fmaxf(fmaxf(v2.x, v2.y), fmaxf(v2.z, v2.w)));
#pragma unroll
        for (int o = 16; o; o >>= 1) rm = fmaxf(rm, __shfl_xor_sync(~0u, rm, o));
        if (lane == 0) g_rm[b * TT + m0 + row] = rm;
    }

    // fused column softmax partials: one column per thread over 64 rows
    int col = tid;
    float cval = c_s[col];
    float m = -3.0e38f, s = 0.f;
#pragma unroll 1
    for (int r = 0; r < 64; r++) {
        float v = Su[r * 260 + col] + a_s[r] + cval;
        if (v > m) { s = s * __expf(m - v) + 1.f; m = v; }
        else s += __expf(v - m);
    }
    g_pm[(b * 16 + mt) * JJ + col] = m;
    g_ps[(b * 16 + mt) * JJ + col] = s;
}

// ---------------------------------------------------------------------------
// K3: b_t = softmax_t(rowmax); h[b,d] = sum_t b_t * ctx
// ---------------------------------------------------------------------------
__global__ __launch_bounds__(128) void bth_kernel(const float* __restrict__ ctx) {
    int b = blockIdx.y, q = blockIdx.x, tid = threadIdx.x;
    int wid = tid >> 5, lane = tid & 31;
    __shared__ float e_s[TT];
    __shared__ float red_m[4], red_s[4];
    float v[8];
    float m = -3.0e38f;
#pragma unroll
    for (int i = 0; i < 8; i++) {
        v[i] = g_rm[b * TT + tid + i * 128];
        m = fmaxf(m, v[i]);
    }
#pragma unroll
    for (int o = 16; o; o >>= 1) m = fmaxf(m, __shfl_xor_sync(~0u, m, o));
    if (lane == 0) red_m[wid] = m;
    __syncthreads();
    m = fmaxf(fmaxf(red_m[0], red_m[1]), fmaxf(red_m[2], red_m[3]));
    float s = 0.f;
#pragma unroll
    for (int i = 0; i < 8; i++) {
        float e = __expf(v[i] - m);
        e_s[tid + i * 128] = e;
        s += e;
    }
#pragma unroll
    for (int o = 16; o; o >>= 1) s += __shfl_xor_sync(~0u, s, o);
    if (lane == 0) red_s[wid] = s;
    __syncthreads();
    float inv = 1.f / (red_s[0] + red_s[1] + red_s[2] + red_s[3]);
    int d = q * 128 + tid;
    const float* cb = ctx + (size_t)b * TT * DD + d;
    float a0 = 0.f, a1 = 0.f, a2 = 0.f, a3 = 0.f;
    for (int t = 0; t < TT; t += 4) {
        a0 += e_s[t + 0] * cb[(size_t)(t + 0) * DD];
        a1 += e_s[t + 1] * cb[(size_t)(t + 1) * DD];
        a2 += e_s[t + 2] * cb[(size_t)(t + 2) * DD];
        a3 += e_s[t + 3] * cb[(size_t)(t + 3) * DD];
    }
    g_h[b * DD + d] = (a0 + a1 + a2 + a3) * inv;
}

// ---------------------------------------------------------------------------
// K4: GEMM2 (fp16 WMMA, 256 thr, 2 CTA/SM): U tile 64x256 = softmax_col(S) @ q
//     colstats combine in prologue; fused G epilogue
// ---------------------------------------------------------------------------
__global__ __launch_bounds__(256, 2) void gemm2_wmma(const float* __restrict__ ctx,
                                                     float* __restrict__ out) {
    extern __shared__ __align__(16) char smc[];
    int tid = threadIdx.x;
    int wid = tid >> 5, wm = wid >> 2, wn = wid & 3;
    int lane = tid & 31;
    int b = blockIdx.z, m0 = blockIdx.y * 64, n0 = blockIdx.x * 256;

    float* cm_s = (float*)(smc + G2_CM);
    float* ci_s = (float*)(smc + G2_CI);
    float* h_s = (float*)(smc + G2_HS);
    {
        float M = -3.0e38f;
#pragma unroll
        for (int p = 0; p < 16; p++) M = fmaxf(M, g_pm[(b * 16 + p) * JJ + tid]);
        float S = 0.f;
#pragma unroll
        for (int p = 0; p < 16; p++)
            S += g_ps[(b * 16 + p) * JJ + tid] * __expf(g_pm[(b * 16 + p) * JJ + tid] - M);
        cm_s[tid] = M;
        ci_s[tid] = 1.f / S;
        h_s[tid] = g_h[b * DD + n0 + tid];
    }
    __syncthreads();

    const float* Sg = g_S + (size_t)(b * TT + m0) * JJ;
    const __half* Bg = g_Bf16 + (size_t)b * JJ * DD + n0;
    uint32_t sm0 = smem_u32(smc);

    AccFrag acc[2][4];
#pragma unroll
    for (int i = 0; i < 2; i++)
#pragma unroll
        for (int j = 0; j < 4; j++) wmma::fill_fragment(acc[i][j], 0.f);

    auto load_stage = [&](int stg, int kc) {
#pragma unroll 1
        for (int i = tid; i < 1024; i += 256) {
            int row = i >> 5, seg = i & 31;
            cpa16(sm0 + stg + MATA + row * 528 + seg * 16,
                  Bg + (size_t)(kc + row) * DD + seg * 8);
        }
        cpa_commit();
#pragma unroll 1
        for (int i = tid; i < 512; i += 256) {
            int row = i >> 3, c4 = (i & 7) * 4;
            int jb = kc + c4;
            float4 v = *(const float4*)(Sg + (size_t)row * JJ + jb);
            float p0 = __expf(v.x - cm_s[jb + 0]) * ci_s[jb + 0];
            float p1 = __expf(v.y - cm_s[jb + 1]) * ci_s[jb + 1];
            float p2 = __expf(v.z - cm_s[jb + 2]) * ci_s[jb + 2];
            float p3 = __expf(v.w - cm_s[jb + 3]) * ci_s[jb + 3];
            *(uint2*)(smc + stg + row * 80 + c4 * 2) = pack4h(p0, p1, p2, p3);
        }
    };

    load_stage(0, 0);
    for (int c = 0; c < 8; c++) {
        int cb = (c & 1) * STG2;
        if (c + 1 < 8) {
            load_stage(((c + 1) & 1) * STG2, (c + 1) * 32);
            cpa_wait<1>();
        } else {
            cpa_wait<0>();
        }
        __syncthreads();
        chunk_g2(smc, cb, wm, wn, acc);
        __syncthreads();
    }

    // epilogue: stage U (64x256, ld 260), fused G = [ctx, U, ctx*U, ctx*h]
    float* Su = (float*)smc;
#pragma unroll
    for (int i = 0; i < 2; i++)
#pragma unroll
        for (int j = 0; j < 4; j++)
            wmma::store_matrix_sync(Su + (wm * 32 + i * 16) * 260 + wn * 64 + j * 16,
                                    acc[i][j], 260, wmma::mem_row_major);
    __syncthreads();
    int c4a = lane * 4, c4b = 128 + lane * 4;
#pragma unroll 1
    for (int r0 = 0; r0 < 64; r0 += 8) {
        int row = r0 + wid;
        const float* crow = ctx + (size_t)(b * TT + m0 + row) * DD + n0;
        float* og = out + (size_t)(b * TT + m0 + row) * 2048 + n0;
#pragma unroll
        for (int half = 0; half < 2; half++) {
            int c4 = half ? c4b : c4a;
            float4 u = *(float4*)&Su[row * 260 + c4];
            float4 cx = *(const float4*)(crow + c4);
            float4 h4 = *(float4*)&h_s[c4];
            float4 cu, ch;
            cu.x = cx.x * u.x; cu.y = cx.y * u.y; cu.z = cx.z * u.z; cu.w = cx.w * u.w;
            ch.x = cx.x * h4.x; ch.y = cx.y * h4.y; ch.z = cx.z * h4.z; ch.w = cx.w * h4.w;
            *(float4*)(og + c4) = cx;
            *(float4*)(og + 512 + c4) = u;
            *(float4*)(og + 1024 + c4) = cu;
            *(float4*)(og + 1536 + c4) = ch;
        }
    }
}

// ---------------------------------------------------------------------------
extern "C" void kernel_launch(void* const* d_in, const int* in_sizes, int n_in,
                              void* d_out, int out_size) {
    const float* ctx = (const float*)d_in[0];
    const float* qry = (const float*)d_in[1];
    const float* w = (const float*)d_in[2];
    float* out = (float*)d_out;

    cudaFuncSetAttribute(gemm1_wmma, cudaFuncAttributeMaxDynamicSharedMemorySize, SMB1);
    cudaFuncSetAttribute(gemm2_wmma, cudaFuncAttributeMaxDynamicSharedMemorySize, SMB2);

    convert_kernel<<<(BB * TT + BB * JJ) / 8, 256>>>(ctx, qry, w);
    gemm1_wmma<<<dim3(TT / 64, BB), 256, SMB1>>>();
    bth_kernel<<<dim3(4, BB), 128>>>(ctx);
    gemm2_wmma<<<dim3(DD / 256, TT / 64, BB), 256, SMB2>>>(ctx, out);
}

// round 15
// speedup vs baseline: 1.5018x; 1.0740x over previous
#include <cuda_runtime.h>
#include <cuda_fp16.h>
#include <mma.h>
#include <stdint.h>
#include <math.h>

using namespace nvcuda;

#define BB 32
#define TT 1024
#define JJ 256
#define DD 512

// ------------------- device scratch (no runtime alloc) ----------------------
__device__ float g_S[(size_t)BB * TT * JJ];
__device__ __half g_Af16[(size_t)BB * TT * DD];  // fp16(ctx*w3)
__device__ __half g_Bf16[(size_t)BB * JJ * DD];  // fp16(q) [b,j,d]
__device__ float g_a[BB * TT], g_c[BB * JJ];
__device__ float g_rm[BB * TT];
__device__ float g_h[BB * DD];
__device__ float g_pm[BB * 16 * JJ], g_ps[BB * 16 * JJ];

// ------------------------------ helpers -------------------------------------
__device__ __forceinline__ uint32_t smem_u32(const void* p) {
    uint32_t a;
    asm("{ .reg .u64 t; cvta.to.shared.u64 t, %1; cvt.u32.u64 %0, t; }"
        : "=r"(a) : "l"(p));
    return a;
}
__device__ __forceinline__ void cpa16(uint32_t d, const void* s) {
    asm volatile("cp.async.cg.shared.global [%0], [%1], 16;" :: "r"(d), "l"(s));
}
__device__ __forceinline__ void cpa_commit() {
    asm volatile("cp.async.commit_group;" ::: "memory");
}
template <int N>
__device__ __forceinline__ void cpa_wait() {
    asm volatile("cp.async.wait_group %0;" :: "n"(N) : "memory");
}

__device__ __forceinline__ uint2 pack4h(float x0, float x1, float x2, float x3) {
    __half2 u = __floats2half2_rn(x0, x1);
    __half2 v = __floats2half2_rn(x2, x3);
    uint2 r;
    r.x = *(uint32_t*)&u;
    r.y = *(uint32_t*)&v;
    return r;
}

// ------------------------- layout constants ---------------------------------
#define LDSA 40        // 32 k + 8 pad halves (80B rows)
#define MATA 5120      // 64*40*2
// gemm1: 3-stage; stage = A(5120) + B(256x40x2 = 20480)
#define MATB1 20480
#define STG1 25600
#define G1_AS 76800    // after 3 stages (Su 66560 overlays stage region)
#define G1_CS (G1_AS + 256)
#define SMB1 (G1_CS + 1024)
// gemm2: probs cache 8 chunks x 5120 = 40960; B double-buffer 2 x 16896
#define PCH 5120
#define B2_OFF 40960
#define LDSB2 264
#define MATB2 16896
#define G2_CM 74752
#define G2_CI (G2_CM + 1024)
#define G2_HS (G2_CI + 1024)  // 512 floats
#define SMB2 (G2_HS + 2048)

typedef wmma::fragment<wmma::accumulator, 16, 16, 16, float> AccFrag;
typedef wmma::fragment<wmma::matrix_a, 16, 16, 16, __half, wmma::row_major> AFrag;
typedef wmma::fragment<wmma::matrix_b, 16, 16, 16, __half, wmma::col_major> BFragC;
typedef wmma::fragment<wmma::matrix_b, 16, 16, 16, __half, wmma::row_major> BFragR;

// one K=32 chunk, gemm1 flavor (B col-major [n][k]); warp tile 32x64
__device__ __forceinline__ void chunk_g1(const char* smc, int bo, int wm, int wn,
                                         AccFrag acc[2][4]) {
    const __half* A = (const __half*)(smc + bo);
    const __half* B = (const __half*)(smc + bo + MATA);
#pragma unroll
    for (int k0 = 0; k0 < 32; k0 += 16) {
        AFrag a[2];
#pragma unroll
        for (int i = 0; i < 2; i++)
            wmma::load_matrix_sync(a[i], A + (wm * 32 + i * 16) * LDSA + k0, LDSA);
#pragma unroll
        for (int jh = 0; jh < 2; jh++) {
            BFragC b[2];
#pragma unroll
            for (int j = 0; j < 2; j++)
                wmma::load_matrix_sync(b[j], B + (wn * 64 + jh * 32 + j * 16) * LDSA + k0, LDSA);
#pragma unroll
            for (int i = 0; i < 2; i++)
#pragma unroll
                for (int j = 0; j < 2; j++)
                    wmma::mma_sync(acc[i][jh * 2 + j], a[i], b[j], acc[i][jh * 2 + j]);
        }
    }
}

// one K=32 chunk, gemm2 flavor (A at aoff, B row-major [k][n] at boff)
__device__ __forceinline__ void chunk_g2(const char* smc, int aoff, int boff,
                                         int wm, int wn, AccFrag acc[2][4]) {
    const __half* A = (const __half*)(smc + aoff);
    const __half* B = (const __half*)(smc + boff);
#pragma unroll
    for (int k0 = 0; k0 < 32; k0 += 16) {
        AFrag a[2];
#pragma unroll
        for (int i = 0; i < 2; i++)
            wmma::load_matrix_sync(a[i], A + (wm * 32 + i * 16) * LDSA + k0, LDSA);
#pragma unroll
        for (int jh = 0; jh < 2; jh++) {
            BFragR b[2];
#pragma unroll
            for (int j = 0; j < 2; j++)
                wmma::load_matrix_sync(b[j], B + k0 * LDSB2 + wn * 64 + jh * 32 + j * 16, LDSB2);
#pragma unroll
            for (int i = 0; i < 2; i++)
#pragma unroll
                for (int j = 0; j < 2; j++)
                    wmma::mma_sync(acc[i][jh * 2 + j], a[i], b[j], acc[i][jh * 2 + j]);
        }
    }
}

// ---------------------------------------------------------------------------
// K1: Af16 = fp16(ctx*w3), a = ctx.w1 ; Bf16 = fp16(q), c = q.w2
// ---------------------------------------------------------------------------
__global__ void convert_kernel(const float* __restrict__ ctx,
                               const float* __restrict__ qry,
                               const float* __restrict__ w) {
    int gw = (blockIdx.x * blockDim.x + threadIdx.x) >> 5;
    int lane = threadIdx.x & 31;
    if (gw < BB * TT) {
        const float* row = ctx + (size_t)gw * DD;
        float acc = 0.f;
#pragma unroll
        for (int i = 0; i < 4; i++) {
            int col = i * 128 + lane * 4;
            float4 x = *(const float4*)(row + col);
            float4 w1v = *(const float4*)(w + col);
            acc += x.x * w1v.x + x.y * w1v.y + x.z * w1v.z + x.w * w1v.w;
            float4 w3v = *(const float4*)(w + 2 * DD + col);
            uint2 hv = pack4h(x.x * w3v.x, x.y * w3v.y, x.z * w3v.z, x.w * w3v.w);
            *(uint2*)((char*)g_Af16 + ((size_t)gw * DD + col) * 2) = hv;
        }
#pragma unroll
        for (int o = 16; o; o >>= 1) acc += __shfl_xor_sync(~0u, acc, o);
        if (lane == 0) g_a[gw] = acc;
    } else {
        int r = gw - BB * TT;
        if (r >= BB * JJ) return;
        const float* row = qry + (size_t)r * DD;
        float acc = 0.f;
#pragma unroll
        for (int i = 0; i < 4; i++) {
            int col = i * 128 + lane * 4;
            float4 x = *(const float4*)(row + col);
            float4 w2v = *(const float4*)(w + DD + col);
            acc += x.x * w2v.x + x.y * w2v.y + x.z * w2v.z + x.w * w2v.w;
            uint2 hv = pack4h(x.x, x.y, x.z, x.w);
            *(uint2*)((char*)g_Bf16 + ((size_t)r * DD + col) * 2) = hv;
        }
#pragma unroll
        for (int o = 16; o; o >>= 1) acc += __shfl_xor_sync(~0u, acc, o);
        if (lane == 0) g_c[r] = acc;
    }
}

// ---------------------------------------------------------------------------
// K2: GEMM1 (fp16 WMMA, 256 thr, 2 CTA/SM, 3-stage): S[b, m0:+64, 0:256]
//     fused rowmax + fused column softmax partials (16 per b)
// ---------------------------------------------------------------------------
__global__ __launch_bounds__(256, 2) void gemm1_wmma() {
    extern __shared__ __align__(16) char smc[];
    int tid = threadIdx.x;
    int wid = tid >> 5, wm = wid >> 2, wn = wid & 3;
    int lane = tid & 31;
    int b = blockIdx.y, mt = blockIdx.x, m0 = mt * 64;

    float* a_s = (float*)(smc + G1_AS);
    float* c_s = (float*)(smc + G1_CS);
    if (tid < 64) a_s[tid] = g_a[b * TT + m0 + tid];
    c_s[tid] = g_c[b * JJ + tid];

    const __half* Ag = g_Af16 + (size_t)(b * TT + m0) * DD;
    const __half* Bg = g_Bf16 + (size_t)b * JJ * DD;
    uint32_t sm0 = smem_u32(smc);

    AccFrag acc[2][4];
#pragma unroll
    for (int i = 0; i < 2; i++)
#pragma unroll
        for (int j = 0; j < 4; j++) wmma::fill_fragment(acc[i][j], 0.f);

    auto load_stage = [&](int sidx, int kc) {
        int stg = sidx * STG1;
#pragma unroll 1
        for (int i = tid; i < 256; i += 256) {
            int row = i >> 2, seg = i & 3;
            cpa16(sm0 + stg + row * 80 + seg * 16, Ag + (size_t)row * DD + kc + seg * 8);
        }
#pragma unroll 1
        for (int i = tid; i < 1024; i += 256) {
            int row = i >> 2, seg = i & 3;
            cpa16(sm0 + stg + MATA + row * 80 + seg * 16, Bg + (size_t)row * DD + kc + seg * 8);
        }
        cpa_commit();
    };

    load_stage(0, 0);
    load_stage(1, 32);
    for (int c = 0; c < 16; c++) {
        int cb = (c % 3) * STG1;
        if (c + 2 < 16) {
            load_stage((c + 2) % 3, (c + 2) * 32);
            cpa_wait<2>();
        } else if (c + 1 < 16) {
            cpa_wait<1>();
        } else {
            cpa_wait<0>();
        }
        __syncthreads();
        chunk_g1(smc, cb, wm, wn, acc);
        __syncthreads();
    }

    // epilogue: stage 64x256 (ld 260, overlays stage region), bias, write + rowmax
    float* Su = (float*)smc;
#pragma unroll
    for (int i = 0; i < 2; i++)
#pragma unroll
        for (int j = 0; j < 4; j++)
            wmma::store_matrix_sync(Su + (wm * 32 + i * 16) * 260 + wn * 64 + (j >> 1) * 32 + (j & 1) * 16,
                                    acc[i][j], 260, wmma::mem_row_major);
    __syncthreads();
    float* Sg = g_S + (size_t)(b * TT + m0) * JJ;
    int c4a = lane * 4, c4b = 128 + lane * 4;
#pragma unroll 1
    for (int r0 = 0; r0 < 64; r0 += 8) {
        int row = r0 + wid;
        float av = a_s[row];
        float4 v1 = *(float4*)&Su[row * 260 + c4a];
        float4 cv1 = *(float4*)&c_s[c4a];
        v1.x += av + cv1.x; v1.y += av + cv1.y; v1.z += av + cv1.z; v1.w += av + cv1.w;
        float4 v2 = *(float4*)&Su[row * 260 + c4b];
        float4 cv2 = *(float4*)&c_s[c4b];
        v2.x += av + cv2.x; v2.y += av + cv2.y; v2.z += av + cv2.z; v2.w += av + cv2.w;
        *(float4*)(Sg + (size_t)row * JJ + c4a) = v1;
        *(float4*)(Sg + (size_t)row * JJ + c4b) = v2;
        float rm = fmaxf(fmaxf(fmaxf(v1.x, v1.y), fmaxf(v1.z, v1.w)),
                         fmaxf(fmaxf(v2.x, v2.y), fmaxf(v2.z, v2.w)));
#pragma unroll
        for (int o = 16; o; o >>= 1) rm = fmaxf(rm, __shfl_xor_sync(~0u, rm, o));
        if (lane == 0) g_rm[b * TT + m0 + row] = rm;
    }

    // fused column softmax partials: one column per thread over 64 rows
    int col = tid;
    float cval = c_s[col];
    float m = -3.0e38f, s = 0.f;
#pragma unroll 1
    for (int r = 0; r < 64; r++) {
        float v = Su[r * 260 + col] + a_s[r] + cval;
        if (v > m) { s = s * __expf(m - v) + 1.f; m = v; }
        else s += __expf(v - m);
    }
    g_pm[(b * 16 + mt) * JJ + col] = m;
    g_ps[(b * 16 + mt) * JJ + col] = s;
}

// ---------------------------------------------------------------------------
// K3: b_t = softmax_t(rowmax); h[b,d] = sum_t b_t * ctx
// ---------------------------------------------------------------------------
__global__ __launch_bounds__(128) void bth_kernel(const float* __restrict__ ctx) {
    int b = blockIdx.y, q = blockIdx.x, tid = threadIdx.x;
    int wid = tid >> 5, lane = tid & 31;
    __shared__ float e_s[TT];
    __shared__ float red_m[4], red_s[4];
    float v[8];
    float m = -3.0e38f;
#pragma unroll
    for (int i = 0; i < 8; i++) {
        v[i] = g_rm[b * TT + tid + i * 128];
        m = fmaxf(m, v[i]);
    }
#pragma unroll
    for (int o = 16; o; o >>= 1) m = fmaxf(m, __shfl_xor_sync(~0u, m, o));
    if (lane == 0) red_m[wid] = m;
    __syncthreads();
    m = fmaxf(fmaxf(red_m[0], red_m[1]), fmaxf(red_m[2], red_m[3]));
    float s = 0.f;
#pragma unroll
    for (int i = 0; i < 8; i++) {
        float e = __expf(v[i] - m);
        e_s[tid + i * 128] = e;
        s += e;
    }
#pragma unroll
    for (int o = 16; o; o >>= 1) s += __shfl_xor_sync(~0u, s, o);
    if (lane == 0) red_s[wid] = s;
    __syncthreads();
    float inv = 1.f / (red_s[0] + red_s[1] + red_s[2] + red_s[3]);
    int d = q * 128 + tid;
    const float* cb = ctx + (size_t)b * TT * DD + d;
    float a0 = 0.f, a1 = 0.f, a2 = 0.f, a3 = 0.f;
    for (int t = 0; t < TT; t += 4) {
        a0 += e_s[t + 0] * cb[(size_t)(t + 0) * DD];
        a1 += e_s[t + 1] * cb[(size_t)(t + 1) * DD];
        a2 += e_s[t + 2] * cb[(size_t)(t + 2) * DD];
        a3 += e_s[t + 3] * cb[(size_t)(t + 3) * DD];
    }
    g_h[b * DD + d] = (a0 + a1 + a2 + a3) * inv;
}

// ---------------------------------------------------------------------------
// K4: GEMM2 (fp16 WMMA, 256 thr, 2 CTA/SM): one CTA per (b, 64-row m-tile)
//     covers the FULL N=512 in two phases with a persistent probs cache.
// ---------------------------------------------------------------------------
__global__ __launch_bounds__(256, 2) void gemm2_wmma(const float* __restrict__ ctx,
                                                     float* __restrict__ out) {
    extern __shared__ __align__(16) char smc[];
    int tid = threadIdx.x;
    int wid = tid >> 5, wm = wid >> 2, wn = wid & 3;
    int lane = tid & 31;
    int b = blockIdx.y, m0 = blockIdx.x * 64;

    float* cm_s = (float*)(smc + G2_CM);
    float* ci_s = (float*)(smc + G2_CI);
    float* h_s = (float*)(smc + G2_HS);
    {
        float M = -3.0e38f;
#pragma unroll
        for (int p = 0; p < 16; p++) M = fmaxf(M, g_pm[(b * 16 + p) * JJ + tid]);
        float S = 0.f;
#pragma unroll
        for (int p = 0; p < 16; p++)
            S += g_ps[(b * 16 + p) * JJ + tid] * __expf(g_pm[(b * 16 + p) * JJ + tid] - M);
        cm_s[tid] = M;
        ci_s[tid] = 1.f / S;
        h_s[tid] = g_h[b * DD + tid];
        h_s[tid + 256] = g_h[b * DD + 256 + tid];
    }
    __syncthreads();

    const float* Sg = g_S + (size_t)(b * TT + m0) * JJ;
    const __half* Bg = g_Bf16 + (size_t)b * JJ * DD;
    uint32_t sm0 = smem_u32(smc);

    AccFrag acc[2][4];
#pragma unroll
    for (int i = 0; i < 2; i++)
#pragma unroll
        for (int j = 0; j < 4; j++) wmma::fill_fragment(acc[i][j], 0.f);

    // B chunk loader (n-half selected by nb), into double buffer
    auto loadB = [&](int c, int nb) {
        int kc = c * 32;
#pragma unroll 1
        for (int i = tid; i < 1024; i += 256) {
            int row = i >> 5, seg = i & 31;
            cpa16(sm0 + B2_OFF + (c & 1) * MATB2 + row * 528 + seg * 16,
                  Bg + (size_t)(kc + row) * DD + nb + seg * 8);
        }
        cpa_commit();
    };
    // probs chunk compute into persistent cache (phase A only)
    auto calcP = [&](int c) {
        int kc = c * 32;
#pragma unroll 1
        for (int i = tid; i < 512; i += 256) {
            int row = i >> 3, c4 = (i & 7) * 4;
            int jb = kc + c4;
            float4 v = *(const float4*)(Sg + (size_t)row * JJ + jb);
            float p0 = __expf(v.x - cm_s[jb + 0]) * ci_s[jb + 0];
            float p1 = __expf(v.y - cm_s[jb + 1]) * ci_s[jb + 1];
            float p2 = __expf(v.z - cm_s[jb + 2]) * ci_s[jb + 2];
            float p3 = __expf(v.w - cm_s[jb + 3]) * ci_s[jb + 3];
            *(uint2*)(smc + c * PCH + row * 80 + c4 * 2) = pack4h(p0, p1, p2, p3);
        }
    };
    // fused G epilogue for one n-half; stages 32 rows at a time over Bbuf area
    auto epilogue = [&](int nb) {
        float* Su = (float*)(smc + B2_OFF);
        int c4a = lane * 4, c4b = 128 + lane * 4;
#pragma unroll 1
        for (int rh = 0; rh < 2; rh++) {
            if (wm == rh) {
#pragma unroll
                for (int i = 0; i < 2; i++)
#pragma unroll
                    for (int j = 0; j < 4; j++)
                        wmma::store_matrix_sync(
                            Su + (i * 16) * 260 + wn * 64 + (j >> 1) * 32 + (j & 1) * 16,
                            acc[i][j], 260, wmma::mem_row_major);
            }
            __syncthreads();
#pragma unroll 1
            for (int r0 = 0; r0 < 32; r0 += 8) {
                int row = r0 + wid;
                int grow = b * TT + m0 + rh * 32 + row;
                const float* crow = ctx + (size_t)grow * DD + nb;
                float* og = out + (size_t)grow * 2048 + nb;
#pragma unroll
                for (int half = 0; half < 2; half++) {
                    int c4 = half ? c4b : c4a;
                    float4 u = *(float4*)&Su[row * 260 + c4];
                    float4 cx = *(const float4*)(crow + c4);
                    float4 h4 = *(float4*)&h_s[nb + c4];
                    float4 cu, ch;
                    cu.x = cx.x * u.x; cu.y = cx.y * u.y;
                    cu.z = cx.z * u.z; cu.w = cx.w * u.w;
                    ch.x = cx.x * h4.x; ch.y = cx.y * h4.y;
                    ch.z = cx.z * h4.z; ch.w = cx.w * h4.w;
                    *(float4*)(og + c4) = cx;
                    *(float4*)(og + 512 + c4) = u;
                    *(float4*)(og + 1024 + c4) = cu;
                    *(float4*)(og + 1536 + c4) = ch;
                }
            }
            __syncthreads();
        }
    };

    // ---- Phase A: n = 0..255, compute probs once into cache ----
    loadB(0, 0);
    calcP(0);
    for (int c = 0; c < 8; c++) {
        if (c + 1 < 8) {
            loadB(c + 1, 0);
            calcP(c + 1);
            cpa_wait<1>();
        } else {
            cpa_wait<0>();
        }
        __syncthreads();
        chunk_g2(smc, c * PCH, B2_OFF + (c & 1) * MATB2, wm, wn, acc);
        __syncthreads();
    }
    epilogue(0);

    // ---- Phase B: n = 256..511, reuse cached probs ----
#pragma unroll
    for (int i = 0; i < 2; i++)
#pragma unroll
        for (int j = 0; j < 4; j++) wmma::fill_fragment(acc[i][j], 0.f);
    loadB(0, 256);
    for (int c = 0; c < 8; c++) {
        if (c + 1 < 8) {
            loadB(c + 1, 256);
            cpa_wait<1>();
        } else {
            cpa_wait<0>();
        }
        __syncthreads();
        chunk_g2(smc, c * PCH, B2_OFF + (c & 1) * MATB2, wm, wn, acc);
        __syncthreads();
    }
    epilogue(256);
}

// ---------------------------------------------------------------------------
extern "C" void kernel_launch(void* const* d_in, const int* in_sizes, int n_in,
                              void* d_out, int out_size) {
    const float* ctx = (const float*)d_in[0];
    const float* qry = (const float*)d_in[1];
    const float* w = (const float*)d_in[2];
    float* out = (float*)d_out;

    cudaFuncSetAttribute(gemm1_wmma, cudaFuncAttributeMaxDynamicSharedMemorySize, SMB1);
    cudaFuncSetAttribute(gemm2_wmma, cudaFuncAttributeMaxDynamicSharedMemorySize, SMB2);

    convert_kernel<<<(BB * TT + BB * JJ) / 8, 256>>>(ctx, qry, w);
    gemm1_wmma<<<dim3(TT / 64, BB), 256, SMB1>>>();
    bth_kernel<<<dim3(4, BB), 128>>>(ctx);
    gemm2_wmma<<<dim3(TT / 64, BB), 256, SMB2>>>(ctx, out);
}

// round 16
// speedup vs baseline: 1.7400x; 1.1586x over previous
#include <cuda_runtime.h>
#include <cuda_fp16.h>
#include <mma.h>
#include <stdint.h>
#include <math.h>

using namespace nvcuda;

#define BB 32
#define TT 1024
#define JJ 256
#define DD 512

// ------------------- device scratch (no runtime alloc) ----------------------
__device__ float g_S[(size_t)BB * TT * JJ];
__device__ __half g_Bf16[(size_t)BB * JJ * DD];  // fp16(q) [b,j,d]
__device__ float g_c[BB * JJ];
__device__ float g_rm[BB * TT];                  // rowmax -> normalized b_t
__device__ float g_hp[4 * BB * DD];              // h partials (t-chunks)
__device__ float g_pm[BB * 16 * JJ], g_ps[BB * 16 * JJ];

// ------------------------------ helpers -------------------------------------
__device__ __forceinline__ uint32_t smem_u32(const void* p) {
    uint32_t a;
    asm("{ .reg .u64 t; cvta.to.shared.u64 t, %1; cvt.u32.u64 %0, t; }"
        : "=r"(a) : "l"(p));
    return a;
}
__device__ __forceinline__ void cpa16(uint32_t d, const void* s) {
    asm volatile("cp.async.cg.shared.global [%0], [%1], 16;" :: "r"(d), "l"(s));
}
__device__ __forceinline__ void cpa_commit() {
    asm volatile("cp.async.commit_group;" ::: "memory");
}
template <int N>
__device__ __forceinline__ void cpa_wait() {
    asm volatile("cp.async.wait_group %0;" :: "n"(N) : "memory");
}

__device__ __forceinline__ uint2 pack4h(float x0, float x1, float x2, float x3) {
    __half2 u = __floats2half2_rn(x0, x1);
    __half2 v = __floats2half2_rn(x2, x3);
    uint2 r;
    r.x = *(uint32_t*)&u;
    r.y = *(uint32_t*)&v;
    return r;
}

// ------------------------- layout constants ---------------------------------
#define LDSA 40        // 32 k + 8 pad halves (80B rows)
#define MATA 5120      // 64*40*2
// gemm1: 3-stage; stage = A(5120) + B(256x40x2 = 20480)
#define MATB1 20480
#define STG1 25600
#define G1_AS 76800    // a_s (64 floats); Su (66560 B) overlays stage region
#define G1_CS (G1_AS + 256)
#define G1_W1 (G1_CS + 1024)
#define G1_W3 (G1_W1 + 2048)
#define SMB1 (G1_W3 + 2048)
// gemm2: probs cache 8 chunks x 5120 = 40960; B double-buffer 2 x 16896
#define PCH 5120
#define B2_OFF 40960
#define LDSB2 264
#define MATB2 16896
#define G2_CM 74752
#define G2_CI (G2_CM + 1024)
#define G2_HS (G2_CI + 1024)  // 512 floats
#define SMB2 (G2_HS + 2048)

typedef wmma::fragment<wmma::accumulator, 16, 16, 16, float> AccFrag;
typedef wmma::fragment<wmma::matrix_a, 16, 16, 16, __half, wmma::row_major> AFrag;
typedef wmma::fragment<wmma::matrix_b, 16, 16, 16, __half, wmma::col_major> BFragC;
typedef wmma::fragment<wmma::matrix_b, 16, 16, 16, __half, wmma::row_major> BFragR;

// one K=32 chunk, gemm1 flavor (B col-major [n][k]); warp tile 32x64
__device__ __forceinline__ void chunk_g1(const char* smc, int bo, int wm, int wn,
                                         AccFrag acc[2][4]) {
    const __half* A = (const __half*)(smc + bo);
    const __half* B = (const __half*)(smc + bo + MATA);
#pragma unroll
    for (int k0 = 0; k0 < 32; k0 += 16) {
        AFrag a[2];
#pragma unroll
        for (int i = 0; i < 2; i++)
            wmma::load_matrix_sync(a[i], A + (wm * 32 + i * 16) * LDSA + k0, LDSA);
#pragma unroll
        for (int jh = 0; jh < 2; jh++) {
            BFragC b[2];
#pragma unroll
            for (int j = 0; j < 2; j++)
                wmma::load_matrix_sync(b[j], B + (wn * 64 + jh * 32 + j * 16) * LDSA + k0, LDSA);
#pragma unroll
            for (int i = 0; i < 2; i++)
#pragma unroll
                for (int j = 0; j < 2; j++)
                    wmma::mma_sync(acc[i][jh * 2 + j], a[i], b[j], acc[i][jh * 2 + j]);
        }
    }
}

// one K=32 chunk, gemm2 flavor (A at aoff, B row-major [k][n] at boff)
__device__ __forceinline__ void chunk_g2(const char* smc, int aoff, int boff,
                                         int wm, int wn, AccFrag acc[2][4]) {
    const __half* A = (const __half*)(smc + aoff);
    const __half* B = (const __half*)(smc + boff);
#pragma unroll
    for (int k0 = 0; k0 < 32; k0 += 16) {
        AFrag a[2];
#pragma unroll
        for (int i = 0; i < 2; i++)
            wmma::load_matrix_sync(a[i], A + (wm * 32 + i * 16) * LDSA + k0, LDSA);
#pragma unroll
        for (int jh = 0; jh < 2; jh++) {
            BFragR b[2];
#pragma unroll
            for (int j = 0; j < 2; j++)
                wmma::load_matrix_sync(b[j], B + k0 * LDSB2 + wn * 64 + jh * 32 + j * 16, LDSB2);
#pragma unroll
            for (int i = 0; i < 2; i++)
#pragma unroll
                for (int j = 0; j < 2; j++)
                    wmma::mma_sync(acc[i][jh * 2 + j], a[i], b[j], acc[i][jh * 2 + j]);
        }
    }
}

// ---------------------------------------------------------------------------
// K1: q-only convert: Bf16 = fp16(q), c = q.w2
// ---------------------------------------------------------------------------
__global__ void convert_q_kernel(const float* __restrict__ qry,
                                 const float* __restrict__ w) {
    int r = (blockIdx.x * blockDim.x + threadIdx.x) >> 5;
    int lane = threadIdx.x & 31;
    if (r >= BB * JJ) return;
    const float* row = qry + (size_t)r * DD;
    float acc = 0.f;
#pragma unroll
    for (int i = 0; i < 4; i++) {
        int col = i * 128 + lane * 4;
        float4 x = *(const float4*)(row + col);
        float4 w2v = *(const float4*)(w + DD + col);
        acc += x.x * w2v.x + x.y * w2v.y + x.z * w2v.z + x.w * w2v.w;
        uint2 hv = pack4h(x.x, x.y, x.z, x.w);
        *(uint2*)((char*)g_Bf16 + ((size_t)r * DD + col) * 2) = hv;
    }
#pragma unroll
    for (int o = 16; o; o >>= 1) acc += __shfl_xor_sync(~0u, acc, o);
    if (lane == 0) g_c[r] = acc;
}

// ---------------------------------------------------------------------------
// K2: GEMM1 (fp16 WMMA, 256 thr, 2 CTA/SM, 3-stage): S[b, m0:+64, 0:256]
//     A converted in-loop from fp32 ctx (* w3); a = ctx.w1 fused;
//     fused rowmax + fused column softmax partials (16 per b)
// ---------------------------------------------------------------------------
__global__ __launch_bounds__(256, 2) void gemm1_wmma(const float* __restrict__ ctx,
                                                     const float* __restrict__ w) {
    extern __shared__ __align__(16) char smc[];
    int tid = threadIdx.x;
    int wid = tid >> 5, wm = wid >> 2, wn = wid & 3;
    int lane = tid & 31;
    int b = blockIdx.y, mt = blockIdx.x, m0 = mt * 64;

    float* a_s = (float*)(smc + G1_AS);
    float* c_s = (float*)(smc + G1_CS);
    float* w1_s = (float*)(smc + G1_W1);
    float* w3_s = (float*)(smc + G1_W3);
    c_s[tid] = g_c[b * JJ + tid];
    w1_s[tid] = w[tid];
    w1_s[256 + tid] = w[256 + tid];
    w3_s[tid] = w[2 * DD + tid];
    w3_s[256 + tid] = w[2 * DD + 256 + tid];
    __syncthreads();

    const float* Ag = ctx + (size_t)(b * TT + m0) * DD;
    const __half* Bg = g_Bf16 + (size_t)b * JJ * DD;
    uint32_t sm0 = smem_u32(smc);
    float a_part = 0.f;

    AccFrag acc[2][4];
#pragma unroll
    for (int i = 0; i < 2; i++)
#pragma unroll
        for (int j = 0; j < 4; j++) wmma::fill_fragment(acc[i][j], 0.f);

    auto load_stage = [&](int sidx, int kc) {
        int stg = sidx * STG1;
        {
            int row = tid >> 2, seg = tid & 3;
            const float* src = Ag + (size_t)row * DD + kc + seg * 8;
            float4 x0 = *(const float4*)src;
            float4 x1 = *(const float4*)(src + 4);
            const float* w3p = &w3_s[kc + seg * 8];
            float4 w30 = *(const float4*)w3p;
            float4 w31 = *(const float4*)(w3p + 4);
            const float* w1p = &w1_s[kc + seg * 8];
            float4 w10 = *(const float4*)w1p;
            float4 w11 = *(const float4*)(w1p + 4);
            a_part += x0.x * w10.x + x0.y * w10.y + x0.z * w10.z + x0.w * w10.w +
                      x1.x * w11.x + x1.y * w11.y + x1.z * w11.z + x1.w * w11.w;
            uint2 h0 = pack4h(x0.x * w30.x, x0.y * w30.y, x0.z * w30.z, x0.w * w30.w);
            uint2 h1 = pack4h(x1.x * w31.x, x1.y * w31.y, x1.z * w31.z, x1.w * w31.w);
            uint4 hv;
            hv.x = h0.x; hv.y = h0.y; hv.z = h1.x; hv.w = h1.y;
            *(uint4*)(smc + stg + row * 80 + seg * 16) = hv;
        }
#pragma unroll 1
        for (int i = tid; i < 1024; i += 256) {
            int row = i >> 2, seg = i & 3;
            cpa16(sm0 + stg + MATA + row * 80 + seg * 16, Bg + (size_t)row * DD + kc + seg * 8);
        }
        cpa_commit();
    };

    load_stage(0, 0);
    load_stage(1, 32);
    for (int c = 0; c < 16; c++) {
        int cb = (c % 3) * STG1;
        if (c + 2 < 16) {
            load_stage((c + 2) % 3, (c + 2) * 32);
            cpa_wait<2>();
        } else if (c + 1 < 16) {
            cpa_wait<1>();
        } else {
            cpa_wait<0>();
        }
        __syncthreads();
        chunk_g1(smc, cb, wm, wn, acc);
        __syncthreads();
    }

    // finish a = ctx.w1 (4 threads per row, same warp)
    a_part += __shfl_xor_sync(~0u, a_part, 1);
    a_part += __shfl_xor_sync(~0u, a_part, 2);
    if ((tid & 3) == 0) a_s[tid >> 2] = a_part;

    // epilogue: stage 64x256 (ld 260, overlays stage region), bias, write + rowmax
    float* Su = (float*)smc;
#pragma unroll
    for (int i = 0; i < 2; i++)
#pragma unroll
        for (int j = 0; j < 4; j++)
            wmma::store_matrix_sync(Su + (wm * 32 + i * 16) * 260 + wn * 64 + (j >> 1) * 32 + (j & 1) * 16,
                                    acc[i][j], 260, wmma::mem_row_major);
    __syncthreads();
    float* Sg = g_S + (size_t)(b * TT + m0) * JJ;
    int c4a = lane * 4, c4b = 128 + lane * 4;
#pragma unroll 1
    for (int r0 = 0; r0 < 64; r0 += 8) {
        int row = r0 + wid;
        float av = a_s[row];
        float4 v1 = *(float4*)&Su[row * 260 + c4a];
        float4 cv1 = *(float4*)&c_s[c4a];
        v1.x += av + cv1.x; v1.y += av + cv1.y; v1.z += av + cv1.z; v1.w += av + cv1.w;
        float4 v2 = *(float4*)&Su[row * 260 + c4b];
        float4 cv2 = *(float4*)&c_s[c4b];
        v2.x += av + cv2.x; v2.y += av + cv2.y; v2.z += av + cv2.z; v2.w += av + cv2.w;
        *(float4*)(Sg + (size_t)row * JJ + c4a) = v1;
        *(float4*)(Sg + (size_t)row * JJ + c4b) = v2;
        float rm = fmaxf(fmaxf(fmaxf(v1.x, v1.y), fmaxf(v1.z, v1.w)),
                         fmaxf(fmaxf(v2.x, v2.y), fmaxf(v2.z, v2.w)));
#pragma unroll
        for (int o = 16; o; o >>= 1) rm = fmaxf(rm, __shfl_xor_sync(~0u, rm, o));
        if (lane == 0) g_rm[b * TT + m0 + row] = rm;
    }

    // fused column softmax partials: one column per thread over 64 rows
    int col = tid;
    float cval = c_s[col];
    float m = -3.0e38f, s = 0.f;
#pragma unroll 1
    for (int r = 0; r < 64; r++) {
        float v = Su[r * 260 + col] + a_s[r] + cval;
        if (v > m) { s = s * __expf(m - v) + 1.f; m = v; }
        else s += __expf(v - m);
    }
    g_pm[(b * 16 + mt) * JJ + col] = m;
    g_ps[(b * 16 + mt) * JJ + col] = s;
}

// ---------------------------------------------------------------------------
// K3: b_t = softmax_t(rowmax), normalized in-place into g_rm
// ---------------------------------------------------------------------------
__global__ __launch_bounds__(256) void bt_kernel() {
    int b = blockIdx.x, tid = threadIdx.x;
    int wid = tid >> 5, lane = tid & 31;
    __shared__ float red_m[8], red_s[8];
    float v[4];
    float m = -3.0e38f;
#pragma unroll
    for (int i = 0; i < 4; i++) {
        v[i] = g_rm[b * TT + tid + i * 256];
        m = fmaxf(m, v[i]);
    }
#pragma unroll
    for (int o = 16; o; o >>= 1) m = fmaxf(m, __shfl_xor_sync(~0u, m, o));
    if (lane == 0) red_m[wid] = m;
    __syncthreads();
    m = red_m[0];
#pragma unroll
    for (int i = 1; i < 8; i++) m = fmaxf(m, red_m[i]);
    float e[4];
    float s = 0.f;
#pragma unroll
    for (int i = 0; i < 4; i++) {
        e[i] = __expf(v[i] - m);
        s += e[i];
    }
#pragma unroll
    for (int o = 16; o; o >>= 1) s += __shfl_xor_sync(~0u, s, o);
    if (lane == 0) red_s[wid] = s;
    __syncthreads();
    float tot = red_s[0];
#pragma unroll
    for (int i = 1; i < 8; i++) tot += red_s[i];
    float inv = 1.f / tot;
#pragma unroll
    for (int i = 0; i < 4; i++) g_rm[b * TT + tid + i * 256] = e[i] * inv;
}

// ---------------------------------------------------------------------------
// K4: h partials: g_hp[tch][b][d] = sum_{t in chunk} b_t[t]*ctx[b,t,d]
// ---------------------------------------------------------------------------
__global__ __launch_bounds__(128) void h_kernel(const float* __restrict__ ctx) {
    int tch = blockIdx.x, dch = blockIdx.y, b = blockIdx.z;
    int d = dch * 128 + threadIdx.x;
    const float* cb = ctx + (size_t)b * TT * DD + (size_t)tch * 256 * DD + d;
    const float* bt = g_rm + b * TT + tch * 256;
    float a0 = 0.f, a1 = 0.f, a2 = 0.f, a3 = 0.f;
#pragma unroll 1
    for (int t = 0; t < 256; t += 4) {
        a0 += bt[t + 0] * cb[(size_t)(t + 0) * DD];
        a1 += bt[t + 1] * cb[(size_t)(t + 1) * DD];
        a2 += bt[t + 2] * cb[(size_t)(t + 2) * DD];
        a3 += bt[t + 3] * cb[(size_t)(t + 3) * DD];
    }
    g_hp[(tch * BB + b) * DD + d] = a0 + a1 + a2 + a3;
}

// ---------------------------------------------------------------------------
// K5: GEMM2 (fp16 WMMA, 256 thr, 2 CTA/SM): one CTA per (b, 64-row m-tile)
//     covers the FULL N=512 in two phases with a persistent probs cache.
// ---------------------------------------------------------------------------
__global__ __launch_bounds__(256, 2) void gemm2_wmma(const float* __restrict__ ctx,
                                                     float* __restrict__ out) {
    extern __shared__ __align__(16) char smc[];
    int tid = threadIdx.x;
    int wid = tid >> 5, wm = wid >> 2, wn = wid & 3;
    int lane = tid & 31;
    int b = blockIdx.y, m0 = blockIdx.x * 64;

    float* cm_s = (float*)(smc + G2_CM);
    float* ci_s = (float*)(smc + G2_CI);
    float* h_s = (float*)(smc + G2_HS);
    {
        float M = -3.0e38f;
#pragma unroll
        for (int p = 0; p < 16; p++) M = fmaxf(M, g_pm[(b * 16 + p) * JJ + tid]);
        float S = 0.f;
#pragma unroll
        for (int p = 0; p < 16; p++)
            S += g_ps[(b * 16 + p) * JJ + tid] * __expf(g_pm[(b * 16 + p) * JJ + tid] - M);
        cm_s[tid] = M;
        ci_s[tid] = 1.f / S;
        float h0 = 0.f, h1 = 0.f;
#pragma unroll
        for (int p = 0; p < 4; p++) {
            h0 += g_hp[(p * BB + b) * DD + tid];
            h1 += g_hp[(p * BB + b) * DD + 256 + tid];
        }
        h_s[tid] = h0;
        h_s[tid + 256] = h1;
    }
    __syncthreads();

    const float* Sg = g_S + (size_t)(b * TT + m0) * JJ;
    const __half* Bg = g_Bf16 + (size_t)b * JJ * DD;
    uint32_t sm0 = smem_u32(smc);

    AccFrag acc[2][4];
#pragma unroll
    for (int i = 0; i < 2; i++)
#pragma unroll
        for (int j = 0; j < 4; j++) wmma::fill_fragment(acc[i][j], 0.f);

    auto loadB = [&](int c, int nb) {
        int kc = c * 32;
#pragma unroll 1
        for (int i = tid; i < 1024; i += 256) {
            int row = i >> 5, seg = i & 31;
            cpa16(sm0 + B2_OFF + (c & 1) * MATB2 + row * 528 + seg * 16,
                  Bg + (size_t)(kc + row) * DD + nb + seg * 8);
        }
        cpa_commit();
    };
    auto calcP = [&](int c) {
        int kc = c * 32;
#pragma unroll 1
        for (int i = tid; i < 512; i += 256) {
            int row = i >> 3, c4 = (i & 7) * 4;
            int jb = kc + c4;
            float4 v = *(const float4*)(Sg + (size_t)row * JJ + jb);
            float p0 = __expf(v.x - cm_s[jb + 0]) * ci_s[jb + 0];
            float p1 = __expf(v.y - cm_s[jb + 1]) * ci_s[jb + 1];
            float p2 = __expf(v.z - cm_s[jb + 2]) * ci_s[jb + 2];
            float p3 = __expf(v.w - cm_s[jb + 3]) * ci_s[jb + 3];
            *(uint2*)(smc + c * PCH + row * 80 + c4 * 2) = pack4h(p0, p1, p2, p3);
        }
    };
    auto epilogue = [&](int nb) {
        float* Su = (float*)(smc + B2_OFF);
        int c4a = lane * 4, c4b = 128 + lane * 4;
#pragma unroll 1
        for (int rh = 0; rh < 2; rh++) {
            if (wm == rh) {
#pragma unroll
                for (int i = 0; i < 2; i++)
#pragma unroll
                    for (int j = 0; j < 4; j++)
                        wmma::store_matrix_sync(
                            Su + (i * 16) * 260 + wn * 64 + (j >> 1) * 32 + (j & 1) * 16,
                            acc[i][j], 260, wmma::mem_row_major);
            }
            __syncthreads();
#pragma unroll 1
            for (int r0 = 0; r0 < 32; r0 += 8) {
                int row = r0 + wid;
                int grow = b * TT + m0 + rh * 32 + row;
                const float* crow = ctx + (size_t)grow * DD + nb;
                float* og = out + (size_t)grow * 2048 + nb;
#pragma unroll
                for (int half = 0; half < 2; half++) {
                    int c4 = half ? c4b : c4a;
                    float4 u = *(float4*)&Su[row * 260 + c4];
                    float4 cx = *(const float4*)(crow + c4);
                    float4 h4 = *(float4*)&h_s[nb + c4];
                    float4 cu, ch;
                    cu.x = cx.x * u.x; cu.y = cx.y * u.y;
                    cu.z = cx.z * u.z; cu.w = cx.w * u.w;
                    ch.x = cx.x * h4.x; ch.y = cx.y * h4.y;
                    ch.z = cx.z * h4.z; ch.w = cx.w * h4.w;
                    *(float4*)(og + c4) = cx;
                    *(float4*)(og + 512 + c4) = u;
                    *(float4*)(og + 1024 + c4) = cu;
                    *(float4*)(og + 1536 + c4) = ch;
                }
            }
            __syncthreads();
        }
    };

    // ---- Phase A: n = 0..255, compute probs once into cache ----
    loadB(0, 0);
    calcP(0);
    for (int c = 0; c < 8; c++) {
        if (c + 1 < 8) {
            loadB(c + 1, 0);
            calcP(c + 1);
            cpa_wait<1>();
        } else {
            cpa_wait<0>();
        }
        __syncthreads();
        chunk_g2(smc, c * PCH, B2_OFF + (c & 1) * MATB2, wm, wn, acc);
        __syncthreads();
    }
    epilogue(0);

    // ---- Phase B: n = 256..511, reuse cached probs ----
#pragma unroll
    for (int i = 0; i < 2; i++)
#pragma unroll
        for (int j = 0; j < 4; j++) wmma::fill_fragment(acc[i][j], 0.f);
    loadB(0, 256);
    for (int c = 0; c < 8; c++) {
        if (c + 1 < 8) {
            loadB(c + 1, 256);
            cpa_wait<1>();
        } else {
            cpa_wait<0>();
        }
        __syncthreads();
        chunk_g2(smc, c * PCH, B2_OFF + (c & 1) * MATB2, wm, wn, acc);
        __syncthreads();
    }
    epilogue(256);
}

// ---------------------------------------------------------------------------
extern "C" void kernel_launch(void* const* d_in, const int* in_sizes, int n_in,
                              void* d_out, int out_size) {
    const float* ctx = (const float*)d_in[0];
    const float* qry = (const float*)d_in[1];
    const float* w = (const float*)d_in[2];
    float* out = (float*)d_out;

    cudaFuncSetAttribute(gemm1_wmma, cudaFuncAttributeMaxDynamicSharedMemorySize, SMB1);
    cudaFuncSetAttribute(gemm2_wmma, cudaFuncAttributeMaxDynamicSharedMemorySize, SMB2);

    convert_q_kernel<<<BB * JJ / 8, 256>>>(qry, w);
    gemm1_wmma<<<dim3(TT / 64, BB), 256, SMB1>>>(ctx, w);
    bt_kernel<<<BB, 256>>>();
    h_kernel<<<dim3(4, 4, BB), 128>>>(ctx);
    gemm2_wmma<<<dim3(TT / 64, BB), 256, SMB2>>>(ctx, out);
}

// round 17
// speedup vs baseline: 1.8335x; 1.0537x over previous
#include <cuda_runtime.h>
#include <cuda_fp16.h>
#include <mma.h>
#include <stdint.h>
#include <math.h>

using namespace nvcuda;

#define BB 32
#define TT 1024
#define JJ 256
#define DD 512

// ------------------- device scratch (no runtime alloc) ----------------------
__device__ float g_S[(size_t)BB * TT * JJ];
__device__ __half g_Bf16[(size_t)BB * JJ * DD];  // fp16(q) [b,j,d]
__device__ float g_c[BB * JJ];
__device__ float g_rm[BB * TT];                  // rowmax -> normalized b_t
__device__ float g_hp[8 * BB * DD];              // h partials (8 t-chunks)
__device__ float g_pm[BB * 16 * JJ], g_ps[BB * 16 * JJ];

// ------------------------------ helpers -------------------------------------
__device__ __forceinline__ uint32_t smem_u32(const void* p) {
    uint32_t a;
    asm("{ .reg .u64 t; cvta.to.shared.u64 t, %1; cvt.u32.u64 %0, t; }"
        : "=r"(a) : "l"(p));
    return a;
}
__device__ __forceinline__ void cpa16(uint32_t d, const void* s) {
    asm volatile("cp.async.cg.shared.global [%0], [%1], 16;" :: "r"(d), "l"(s));
}
__device__ __forceinline__ void cpa_commit() {
    asm volatile("cp.async.commit_group;" ::: "memory");
}
template <int N>
__device__ __forceinline__ void cpa_wait() {
    asm volatile("cp.async.wait_group %0;" :: "n"(N) : "memory");
}

__device__ __forceinline__ uint2 pack4h(float x0, float x1, float x2, float x3) {
    __half2 u = __floats2half2_rn(x0, x1);
    __half2 v = __floats2half2_rn(x2, x3);
    uint2 r;
    r.x = *(uint32_t*)&u;
    r.y = *(uint32_t*)&v;
    return r;
}

// ------------------------- layout constants ---------------------------------
#define LDSA 40        // 32 k + 8 pad halves (80B rows)
#define MATA 5120      // 64*40*2
// gemm1: 3-stage; stage = A(5120) + B(256x40x2 = 20480)
#define MATB1 20480
#define STG1 25600
#define G1_AS 76800    // a_s (64 floats); Su (66560 B) overlays stage region
#define G1_CS (G1_AS + 256)
#define G1_W1 (G1_CS + 1024)
#define G1_W3 (G1_W1 + 2048)
#define SMB1 (G1_W3 + 2048)
// gemm2: probs cache 8 chunks x 5120 = 40960; B double-buffer 2 x 16896
#define PCH 5120
#define B2_OFF 40960
#define LDSB2 264
#define MATB2 16896
#define G2_CM 74752
#define G2_CI (G2_CM + 1024)
#define G2_HS (G2_CI + 1024)  // 512 floats
#define SMB2 (G2_HS + 2048)

typedef wmma::fragment<wmma::accumulator, 16, 16, 16, float> AccFrag;
typedef wmma::fragment<wmma::matrix_a, 16, 16, 16, __half, wmma::row_major> AFrag;
typedef wmma::fragment<wmma::matrix_b, 16, 16, 16, __half, wmma::col_major> BFragC;
typedef wmma::fragment<wmma::matrix_b, 16, 16, 16, __half, wmma::row_major> BFragR;

// one K=32 chunk, gemm1 flavor (B col-major [n][k]); warp tile 32x64
__device__ __forceinline__ void chunk_g1(const char* smc, int bo, int wm, int wn,
                                         AccFrag acc[2][4]) {
    const __half* A = (const __half*)(smc + bo);
    const __half* B = (const __half*)(smc + bo + MATA);
#pragma unroll
    for (int k0 = 0; k0 < 32; k0 += 16) {
        AFrag a[2];
#pragma unroll
        for (int i = 0; i < 2; i++)
            wmma::load_matrix_sync(a[i], A + (wm * 32 + i * 16) * LDSA + k0, LDSA);
#pragma unroll
        for (int jh = 0; jh < 2; jh++) {
            BFragC b[2];
#pragma unroll
            for (int j = 0; j < 2; j++)
                wmma::load_matrix_sync(b[j], B + (wn * 64 + jh * 32 + j * 16) * LDSA + k0, LDSA);
#pragma unroll
            for (int i = 0; i < 2; i++)
#pragma unroll
                for (int j = 0; j < 2; j++)
                    wmma::mma_sync(acc[i][jh * 2 + j], a[i], b[j], acc[i][jh * 2 + j]);
        }
    }
}

// one K=32 chunk, gemm2 flavor (A at aoff, B row-major [k][n] at boff)
__device__ __forceinline__ void chunk_g2(const char* smc, int aoff, int boff,
                                         int wm, int wn, AccFrag acc[2][4]) {
    const __half* A = (const __half*)(smc + aoff);
    const __half* B = (const __half*)(smc + boff);
#pragma unroll
    for (int k0 = 0; k0 < 32; k0 += 16) {
        AFrag a[2];
#pragma unroll
        for (int i = 0; i < 2; i++)
            wmma::load_matrix_sync(a[i], A + (wm * 32 + i * 16) * LDSA + k0, LDSA);
#pragma unroll
        for (int jh = 0; jh < 2; jh++) {
            BFragR b[2];
#pragma unroll
            for (int j = 0; j < 2; j++)
                wmma::load_matrix_sync(b[j], B + k0 * LDSB2 + wn * 64 + jh * 32 + j * 16, LDSB2);
#pragma unroll
            for (int i = 0; i < 2; i++)
#pragma unroll
                for (int j = 0; j < 2; j++)
                    wmma::mma_sync(acc[i][jh * 2 + j], a[i], b[j], acc[i][jh * 2 + j]);
        }
    }
}

// ---------------------------------------------------------------------------
// K1: q-only convert: Bf16 = fp16(q), c = q.w2
// ---------------------------------------------------------------------------
__global__ void convert_q_kernel(const float* __restrict__ qry,
                                 const float* __restrict__ w) {
    int r = (blockIdx.x * blockDim.x + threadIdx.x) >> 5;
    int lane = threadIdx.x & 31;
    if (r >= BB * JJ) return;
    const float* row = qry + (size_t)r * DD;
    float acc = 0.f;
#pragma unroll
    for (int i = 0; i < 4; i++) {
        int col = i * 128 + lane * 4;
        float4 x = *(const float4*)(row + col);
        float4 w2v = *(const float4*)(w + DD + col);
        acc += x.x * w2v.x + x.y * w2v.y + x.z * w2v.z + x.w * w2v.w;
        uint2 hv = pack4h(x.x, x.y, x.z, x.w);
        *(uint2*)((char*)g_Bf16 + ((size_t)r * DD + col) * 2) = hv;
    }
#pragma unroll
    for (int o = 16; o; o >>= 1) acc += __shfl_xor_sync(~0u, acc, o);
    if (lane == 0) g_c[r] = acc;
}

// ---------------------------------------------------------------------------
// K2: GEMM1 (fp16 WMMA, 256 thr, 2 CTA/SM, 3-stage): S[b, m0:+64, 0:256]
//     A converted in-loop from fp32 ctx (* w3); a = ctx.w1 fused;
//     fused rowmax + fused column softmax partials (16 per b)
// ---------------------------------------------------------------------------
__global__ __launch_bounds__(256, 2) void gemm1_wmma(const float* __restrict__ ctx,
                                                     const float* __restrict__ w) {
    extern __shared__ __align__(16) char smc[];
    int tid = threadIdx.x;
    int wid = tid >> 5, wm = wid >> 2, wn = wid & 3;
    int lane = tid & 31;
    int b = blockIdx.y, mt = blockIdx.x, m0 = mt * 64;

    float* a_s = (float*)(smc + G1_AS);
    float* c_s = (float*)(smc + G1_CS);
    float* w1_s = (float*)(smc + G1_W1);
    float* w3_s = (float*)(smc + G1_W3);
    c_s[tid] = g_c[b * JJ + tid];
    w1_s[tid] = w[tid];
    w1_s[256 + tid] = w[256 + tid];
    w3_s[tid] = w[2 * DD + tid];
    w3_s[256 + tid] = w[2 * DD + 256 + tid];
    __syncthreads();

    const float* Ag = ctx + (size_t)(b * TT + m0) * DD;
    const __half* Bg = g_Bf16 + (size_t)b * JJ * DD;
    uint32_t sm0 = smem_u32(smc);
    float a_part = 0.f;

    AccFrag acc[2][4];
#pragma unroll
    for (int i = 0; i < 2; i++)
#pragma unroll
        for (int j = 0; j < 4; j++) wmma::fill_fragment(acc[i][j], 0.f);

    auto load_stage = [&](int sidx, int kc) {
        int stg = sidx * STG1;
        {
            int row = tid >> 2, seg = tid & 3;
            const float* src = Ag + (size_t)row * DD + kc + seg * 8;
            float4 x0 = *(const float4*)src;
            float4 x1 = *(const float4*)(src + 4);
            const float* w3p = &w3_s[kc + seg * 8];
            float4 w30 = *(const float4*)w3p;
            float4 w31 = *(const float4*)(w3p + 4);
            const float* w1p = &w1_s[kc + seg * 8];
            float4 w10 = *(const float4*)w1p;
            float4 w11 = *(const float4*)(w1p + 4);
            a_part += x0.x * w10.x + x0.y * w10.y + x0.z * w10.z + x0.w * w10.w +
                      x1.x * w11.x + x1.y * w11.y + x1.z * w11.z + x1.w * w11.w;
            uint2 h0 = pack4h(x0.x * w30.x, x0.y * w30.y, x0.z * w30.z, x0.w * w30.w);
            uint2 h1 = pack4h(x1.x * w31.x, x1.y * w31.y, x1.z * w31.z, x1.w * w31.w);
            uint4 hv;
            hv.x = h0.x; hv.y = h0.y; hv.z = h1.x; hv.w = h1.y;
            *(uint4*)(smc + stg + row * 80 + seg * 16) = hv;
        }
#pragma unroll 1
        for (int i = tid; i < 1024; i += 256) {
            int row = i >> 2, seg = i & 3;
            cpa16(sm0 + stg + MATA + row * 80 + seg * 16, Bg + (size_t)row * DD + kc + seg * 8);
        }
        cpa_commit();
    };

    load_stage(0, 0);
    load_stage(1, 32);
    for (int c = 0; c < 16; c++) {
        int cb = (c % 3) * STG1;
        if (c + 2 < 16) {
            load_stage((c + 2) % 3, (c + 2) * 32);
            cpa_wait<2>();
        } else if (c + 1 < 16) {
            cpa_wait<1>();
        } else {
            cpa_wait<0>();
        }
        __syncthreads();
        chunk_g1(smc, cb, wm, wn, acc);
        __syncthreads();
    }

    // finish a = ctx.w1 (4 threads per row, same warp)
    a_part += __shfl_xor_sync(~0u, a_part, 1);
    a_part += __shfl_xor_sync(~0u, a_part, 2);
    if ((tid & 3) == 0) a_s[tid >> 2] = a_part;

    // epilogue: stage 64x256 (ld 260, overlays stage region), bias, write + rowmax
    float* Su = (float*)smc;
#pragma unroll
    for (int i = 0; i < 2; i++)
#pragma unroll
        for (int j = 0; j < 4; j++)
            wmma::store_matrix_sync(Su + (wm * 32 + i * 16) * 260 + wn * 64 + (j >> 1) * 32 + (j & 1) * 16,
                                    acc[i][j], 260, wmma::mem_row_major);
    __syncthreads();
    float* Sg = g_S + (size_t)(b * TT + m0) * JJ;
    int c4a = lane * 4, c4b = 128 + lane * 4;
#pragma unroll 1
    for (int r0 = 0; r0 < 64; r0 += 8) {
        int row = r0 + wid;
        float av = a_s[row];
        float4 v1 = *(float4*)&Su[row * 260 + c4a];
        float4 cv1 = *(float4*)&c_s[c4a];
        v1.x += av + cv1.x; v1.y += av + cv1.y; v1.z += av + cv1.z; v1.w += av + cv1.w;
        float4 v2 = *(float4*)&Su[row * 260 + c4b];
        float4 cv2 = *(float4*)&c_s[c4b];
        v2.x += av + cv2.x; v2.y += av + cv2.y; v2.z += av + cv2.z; v2.w += av + cv2.w;
        *(float4*)(Sg + (size_t)row * JJ + c4a) = v1;
        *(float4*)(Sg + (size_t)row * JJ + c4b) = v2;
        float rm = fmaxf(fmaxf(fmaxf(v1.x, v1.y), fmaxf(v1.z, v1.w)),
                         fmaxf(fmaxf(v2.x, v2.y), fmaxf(v2.z, v2.w)));
#pragma unroll
        for (int o = 16; o; o >>= 1) rm = fmaxf(rm, __shfl_xor_sync(~0u, rm, o));
        if (lane == 0) g_rm[b * TT + m0 + row] = rm;
    }

    // fused column softmax partials: one column per thread over 64 rows
    int col = tid;
    float cval = c_s[col];
    float m = -3.0e38f, s = 0.f;
#pragma unroll 1
    for (int r = 0; r < 64; r++) {
        float v = Su[r * 260 + col] + a_s[r] + cval;
        if (v > m) { s = s * __expf(m - v) + 1.f; m = v; }
        else s += __expf(v - m);
    }
    g_pm[(b * 16 + mt) * JJ + col] = m;
    g_ps[(b * 16 + mt) * JJ + col] = s;
}

// ---------------------------------------------------------------------------
// K3: b_t = softmax_t(rowmax), normalized in-place into g_rm
// ---------------------------------------------------------------------------
__global__ __launch_bounds__(256) void bt_kernel() {
    int b = blockIdx.x, tid = threadIdx.x;
    int wid = tid >> 5, lane = tid & 31;
    __shared__ float red_m[8], red_s[8];
    float v[4];
    float m = -3.0e38f;
#pragma unroll
    for (int i = 0; i < 4; i++) {
        v[i] = g_rm[b * TT + tid + i * 256];
        m = fmaxf(m, v[i]);
    }
#pragma unroll
    for (int o = 16; o; o >>= 1) m = fmaxf(m, __shfl_xor_sync(~0u, m, o));
    if (lane == 0) red_m[wid] = m;
    __syncthreads();
    m = red_m[0];
#pragma unroll
    for (int i = 1; i < 8; i++) m = fmaxf(m, red_m[i]);
    float e[4];
    float s = 0.f;
#pragma unroll
    for (int i = 0; i < 4; i++) {
        e[i] = __expf(v[i] - m);
        s += e[i];
    }
#pragma unroll
    for (int o = 16; o; o >>= 1) s += __shfl_xor_sync(~0u, s, o);
    if (lane == 0) red_s[wid] = s;
    __syncthreads();
    float tot = red_s[0];
#pragma unroll
    for (int i = 1; i < 8; i++) tot += red_s[i];
    float inv = 1.f / tot;
#pragma unroll
    for (int i = 0; i < 4; i++) g_rm[b * TT + tid + i * 256] = e[i] * inv;
}

// ---------------------------------------------------------------------------
// K4: h partials, MLP-optimized: one block covers full D row (float4/thread),
//     8 independent float4 accumulators, t-chunk = 128 rows.
//     g_hp[tch][b][d] = sum_{t in chunk} b_t[t]*ctx[b,t,d]
// ---------------------------------------------------------------------------
__global__ __launch_bounds__(128) void h_kernel(const float* __restrict__ ctx) {
    int tch = blockIdx.x, b = blockIdx.y;
    int d4 = threadIdx.x * 4;
    const float* cb = ctx + (size_t)b * TT * DD + (size_t)tch * 128 * DD + d4;
    const float* bt = g_rm + b * TT + tch * 128;

    float4 acc[8];
#pragma unroll
    for (int i = 0; i < 8; i++) acc[i] = make_float4(0.f, 0.f, 0.f, 0.f);

#pragma unroll 1
    for (int t = 0; t < 128; t += 8) {
        float4 x[8];
        float bw[8];
#pragma unroll
        for (int i = 0; i < 8; i++) {
            x[i] = *(const float4*)(cb + (size_t)(t + i) * DD);
            bw[i] = bt[t + i];
        }
#pragma unroll
        for (int i = 0; i < 8; i++) {
            acc[i].x = fmaf(bw[i], x[i].x, acc[i].x);
            acc[i].y = fmaf(bw[i], x[i].y, acc[i].y);
            acc[i].z = fmaf(bw[i], x[i].z, acc[i].z);
            acc[i].w = fmaf(bw[i], x[i].w, acc[i].w);
        }
    }
    float4 r = acc[0];
#pragma unroll
    for (int i = 1; i < 8; i++) {
        r.x += acc[i].x; r.y += acc[i].y; r.z += acc[i].z; r.w += acc[i].w;
    }
    *(float4*)(&g_hp[(tch * BB + b) * DD + d4]) = r;
}

// ---------------------------------------------------------------------------
// K5: GEMM2 (fp16 WMMA, 256 thr, 2 CTA/SM): one CTA per (b, 64-row m-tile)
//     covers the FULL N=512 in two phases with a persistent probs cache.
// ---------------------------------------------------------------------------
__global__ __launch_bounds__(256, 2) void gemm2_wmma(const float* __restrict__ ctx,
                                                     float* __restrict__ out) {
    extern __shared__ __align__(16) char smc[];
    int tid = threadIdx.x;
    int wid = tid >> 5, wm = wid >> 2, wn = wid & 3;
    int lane = tid & 31;
    int b = blockIdx.y, m0 = blockIdx.x * 64;

    float* cm_s = (float*)(smc + G2_CM);
    float* ci_s = (float*)(smc + G2_CI);
    float* h_s = (float*)(smc + G2_HS);
    {
        float M = -3.0e38f;
#pragma unroll
        for (int p = 0; p < 16; p++) M = fmaxf(M, g_pm[(b * 16 + p) * JJ + tid]);
        float S = 0.f;
#pragma unroll
        for (int p = 0; p < 16; p++)
            S += g_ps[(b * 16 + p) * JJ + tid] * __expf(g_pm[(b * 16 + p) * JJ + tid] - M);
        cm_s[tid] = M;
        ci_s[tid] = 1.f / S;
        float h0 = 0.f, h1 = 0.f;
#pragma unroll
        for (int p = 0; p < 8; p++) {
            h0 += g_hp[(p * BB + b) * DD + tid];
            h1 += g_hp[(p * BB + b) * DD + 256 + tid];
        }
        h_s[tid] = h0;
        h_s[tid + 256] = h1;
    }
    __syncthreads();

    const float* Sg = g_S + (size_t)(b * TT + m0) * JJ;
    const __half* Bg = g_Bf16 + (size_t)b * JJ * DD;
    uint32_t sm0 = smem_u32(smc);

    AccFrag acc[2][4];
#pragma unroll
    for (int i = 0; i < 2; i++)
#pragma unroll
        for (int j = 0; j < 4; j++) wmma::fill_fragment(acc[i][j], 0.f);

    auto loadB = [&](int c, int nb) {
        int kc = c * 32;
#pragma unroll 1
        for (int i = tid; i < 1024; i += 256) {
            int row = i >> 5, seg = i & 31;
            cpa16(sm0 + B2_OFF + (c & 1) * MATB2 + row * 528 + seg * 16,
                  Bg + (size_t)(kc + row) * DD + nb + seg * 8);
        }
        cpa_commit();
    };
    auto calcP = [&](int c) {
        int kc = c * 32;
#pragma unroll 1
        for (int i = tid; i < 512; i += 256) {
            int row = i >> 3, c4 = (i & 7) * 4;
            int jb = kc + c4;
            float4 v = *(const float4*)(Sg + (size_t)row * JJ + jb);
            float p0 = __expf(v.x - cm_s[jb + 0]) * ci_s[jb + 0];
            float p1 = __expf(v.y - cm_s[jb + 1]) * ci_s[jb + 1];
            float p2 = __expf(v.z - cm_s[jb + 2]) * ci_s[jb + 2];
            float p3 = __expf(v.w - cm_s[jb + 3]) * ci_s[jb + 3];
            *(uint2*)(smc + c * PCH + row * 80 + c4 * 2) = pack4h(p0, p1, p2, p3);
        }
    };
    auto epilogue = [&](int nb) {
        float* Su = (float*)(smc + B2_OFF);
        int c4a = lane * 4, c4b = 128 + lane * 4;
#pragma unroll 1
        for (int rh = 0; rh < 2; rh++) {
            if (wm == rh) {
#pragma unroll
                for (int i = 0; i < 2; i++)
#pragma unroll
                    for (int j = 0; j < 4; j++)
                        wmma::store_matrix_sync(
                            Su + (i * 16) * 260 + wn * 64 + (j >> 1) * 32 + (j & 1) * 16,
                            acc[i][j], 260, wmma::mem_row_major);
            }
            __syncthreads();
#pragma unroll 1
            for (int r0 = 0; r0 < 32; r0 += 8) {
                int row = r0 + wid;
                int grow = b * TT + m0 + rh * 32 + row;
                const float* crow = ctx + (size_t)grow * DD + nb;
                float* og = out + (size_t)grow * 2048 + nb;
#pragma unroll
                for (int half = 0; half < 2; half++) {
                    int c4 = half ? c4b : c4a;
                    float4 u = *(float4*)&Su[row * 260 + c4];
                    float4 cx = *(const float4*)(crow + c4);
                    float4 h4 = *(float4*)&h_s[nb + c4];
                    float4 cu, ch;
                    cu.x = cx.x * u.x; cu.y = cx.y * u.y;
                    cu.z = cx.z * u.z; cu.w = cx.w * u.w;
                    ch.x = cx.x * h4.x; ch.y = cx.y * h4.y;
                    ch.z = cx.z * h4.z; ch.w = cx.w * h4.w;
                    *(float4*)(og + c4) = cx;
                    *(float4*)(og + 512 + c4) = u;
                    *(float4*)(og + 1024 + c4) = cu;
                    *(float4*)(og + 1536 + c4) = ch;
                }
            }
            __syncthreads();
        }
    };

    // ---- Phase A: n = 0..255, compute probs once into cache ----
    loadB(0, 0);
    calcP(0);
    for (int c = 0; c < 8; c++) {
        if (c + 1 < 8) {
            loadB(c + 1, 0);
            calcP(c + 1);
            cpa_wait<1>();
        } else {
            cpa_wait<0>();
        }
        __syncthreads();
        chunk_g2(smc, c * PCH, B2_OFF + (c & 1) * MATB2, wm, wn, acc);
        __syncthreads();
    }
    epilogue(0);

    // ---- Phase B: n = 256..511, reuse cached probs ----
#pragma unroll
    for (int i = 0; i < 2; i++)
#pragma unroll
        for (int j = 0; j < 4; j++) wmma::fill_fragment(acc[i][j], 0.f);
    loadB(0, 256);
    for (int c = 0; c < 8; c++) {
        if (c + 1 < 8) {
            loadB(c + 1, 256);
            cpa_wait<1>();
        } else {
            cpa_wait<0>();
        }
        __syncthreads();
        chunk_g2(smc, c * PCH, B2_OFF + (c & 1) * MATB2, wm, wn, acc);
        __syncthreads();
    }
    epilogue(256);
}

// ---------------------------------------------------------------------------
extern "C" void kernel_launch(void* const* d_in, const int* in_sizes, int n_in,
                              void* d_out, int out_size) {
    const float* ctx = (const float*)d_in[0];
    const float* qry = (const float*)d_in[1];
    const float* w = (const float*)d_in[2];
    float* out = (float*)d_out;

    cudaFuncSetAttribute(gemm1_wmma, cudaFuncAttributeMaxDynamicSharedMemorySize, SMB1);
    cudaFuncSetAttribute(gemm2_wmma, cudaFuncAttributeMaxDynamicSharedMemorySize, SMB2);

    convert_q_kernel<<<BB * JJ / 8, 256>>>(qry, w);
    gemm1_wmma<<<dim3(TT / 64, BB), 256, SMB1>>>(ctx, w);
    bt_kernel<<<BB, 256>>>();
    h_kernel<<<dim3(8, BB), 128>>>(ctx);
    gemm2_wmma<<<dim3(TT / 64, BB), 256, SMB2>>>(ctx, out);
}